// round 1
// baseline (speedup 1.0000x reference)
#include <cuda_runtime.h>
#include <math.h>

#define BATCH 4
#define TSEQ  4096
#define EMB   100
#define HS    64

// Scratch for projections (static device arrays: allocation-free per harness rules)
__device__ float g_q[BATCH * TSEQ * HS];
__device__ float g_k[BATCH * TSEQ * HS];
__device__ float g_v[BATCH * TSEQ * HS];

// ---------------------------------------------------------------------------
// Kernel 1: fused Q/K/V projection.
// 256 threads = 64 head-dims x 4 row-groups; each thread computes 8 rows for
// one head-dim j across all three matrices (reuses W loads 8x, x via SMEM
// broadcast). Grid: 16384 rows / 32 rows-per-block = 512 blocks.
// ---------------------------------------------------------------------------
__global__ __launch_bounds__(256) void proj_kernel(
    const float* __restrict__ x,
    const float* __restrict__ Wq,
    const float* __restrict__ Wk,
    const float* __restrict__ Wv)
{
    __shared__ float xs[32][EMB];
    const int tid = threadIdx.x;
    const int row0 = blockIdx.x * 32;

    for (int i = tid; i < 32 * EMB; i += 256)
        xs[i / EMB][i % EMB] = x[row0 * EMB + i];
    __syncthreads();

    const int j  = tid & 63;
    const int rg = tid >> 6;   // 0..3, uniform within a warp -> xs reads broadcast

    float q[8], k[8], v[8];
#pragma unroll
    for (int rr = 0; rr < 8; rr++) { q[rr] = 0.f; k[rr] = 0.f; v[rr] = 0.f; }

    for (int e = 0; e < EMB; e++) {
        const float wq = __ldg(&Wq[e * HS + j]);
        const float wk = __ldg(&Wk[e * HS + j]);
        const float wv = __ldg(&Wv[e * HS + j]);
#pragma unroll
        for (int rr = 0; rr < 8; rr++) {
            const float xv = xs[rg * 8 + rr][e];
            q[rr] = fmaf(xv, wq, q[rr]);
            k[rr] = fmaf(xv, wk, k[rr]);
            v[rr] = fmaf(xv, wv, v[rr]);
        }
    }

#pragma unroll
    for (int rr = 0; rr < 8; rr++) {
        const int row = row0 + rg * 8 + rr;
        g_q[row * HS + j] = q[rr];
        g_k[row * HS + j] = k[rr];
        g_v[row * HS + j] = v[rr];
    }
}

// ---------------------------------------------------------------------------
// Kernel 2: causal flash attention, fp32.
// Grid (64, BATCH): one CTA per 64-row Q tile; qt issued descending for
// causal load balance. 256 threads = 64 rows (r) x 4 lane-groups (c).
// Each thread owns 16 score columns (tokens c*16+j) and 16 output dims
// (interleaved mapping d = i4*16 + c*4 + w  -> conflict-free V reads).
// K tile uses an XOR chunk swizzle so QK^T reads hit 4 distinct bank groups.
// ---------------------------------------------------------------------------
__global__ __launch_bounds__(256) void attn_kernel(float* __restrict__ out)
{
    const int qt  = 63 - (int)blockIdx.x;   // heavy tiles first
    const int b   = blockIdx.y;
    const int tid = threadIdx.x;
    const int r    = tid >> 2;              // query row within tile (0..63)
    const int c    = tid & 3;               // lane group (0..3)
    const int lane = tid & 31;
    const unsigned FULL = 0xffffffffu;
    const int base = lane & ~3;             // first lane of this row's 4-lane group

    __shared__ float Ks[64][64];            // [token][swizzled dim]
    __shared__ float Vs[64][64];            // [token][dim]

    const float* qp  = g_q + ((size_t)b * TSEQ + (size_t)qt * 64) * HS;
    const float* kp0 = g_k + (size_t)b * TSEQ * HS;
    const float* vp0 = g_v + (size_t)b * TSEQ * HS;

    // Q row chunk in registers, pre-scaled by 1/sqrt(64)
    float qreg[16];
#pragma unroll
    for (int i = 0; i < 4; i++) {
        float4 t = *(const float4*)(qp + r * HS + c * 16 + i * 4);
        qreg[4 * i + 0] = t.x * 0.125f;
        qreg[4 * i + 1] = t.y * 0.125f;
        qreg[4 * i + 2] = t.z * 0.125f;
        qreg[4 * i + 3] = t.w * 0.125f;
    }

    float m = -INFINITY, l = 0.f;
    float o[16];
#pragma unroll
    for (int i = 0; i < 16; i++) o[i] = 0.f;

    for (int kt = 0; kt <= qt; kt++) {
        __syncthreads();
        const float* kp = kp0 + (size_t)kt * 64 * HS;
        const float* vp = vp0 + (size_t)kt * 64 * HS;
#pragma unroll
        for (int it = 0; it < 4; it++) {
            const int idx  = tid + it * 256;
            const int row  = idx >> 4;       // token 0..63
            const int col4 = idx & 15;       // 16B chunk within the 64-dim row
            float4 kv = *(const float4*)(kp + row * HS + col4 * 4);
            const int sw = ((col4 + (row >> 4)) & 15) * 4;  // XOR-ish chunk swizzle
            *(float4*)(&Ks[row][sw]) = kv;
            float4 vv = *(const float4*)(vp + row * HS + col4 * 4);
            *(float4*)(&Vs[row][col4 * 4]) = vv;
        }
        __syncthreads();

        // ---- S = (Q/8) K^T  for this thread's 16 token columns ----
        float s[16];
#pragma unroll
        for (int i = 0; i < 16; i++) s[i] = 0.f;

#pragma unroll 1
        for (int csrc = 0; csrc < 4; csrc++) {
#pragma unroll
            for (int i4 = 0; i4 < 4; i4++) {
                const float q0 = __shfl_sync(FULL, qreg[i4 * 4 + 0], base + csrc);
                const float q1 = __shfl_sync(FULL, qreg[i4 * 4 + 1], base + csrc);
                const float q2 = __shfl_sync(FULL, qreg[i4 * 4 + 2], base + csrc);
                const float q3 = __shfl_sync(FULL, qreg[i4 * 4 + 3], base + csrc);
                const int chunk = csrc * 4 + i4;     // kk/4
#pragma unroll
                for (int j = 0; j < 16; j++) {
                    const int tok = c * 16 + j;
                    float4 kv = *(const float4*)(&Ks[tok][((chunk + c) & 15) * 4]);
                    s[j] = fmaf(q0, kv.x, s[j]);
                    s[j] = fmaf(q1, kv.y, s[j]);
                    s[j] = fmaf(q2, kv.z, s[j]);
                    s[j] = fmaf(q3, kv.w, s[j]);
                }
            }
        }

        // ---- causal mask on the diagonal tile ----
        if (kt == qt) {
#pragma unroll
            for (int j = 0; j < 16; j++)
                if (c * 16 + j > r) s[j] = -INFINITY;
        }

        // ---- online softmax (row reduction across the 4-lane group) ----
        float tmax = s[0];
#pragma unroll
        for (int j = 1; j < 16; j++) tmax = fmaxf(tmax, s[j]);
        tmax = fmaxf(tmax, __shfl_xor_sync(FULL, tmax, 1));
        tmax = fmaxf(tmax, __shfl_xor_sync(FULL, tmax, 2));
        const float mnew  = fmaxf(m, tmax);
        const float alpha = __expf(m - mnew);
        float lsum = 0.f;
#pragma unroll
        for (int j = 0; j < 16; j++) {
            s[j] = __expf(s[j] - mnew);   // s becomes P
            lsum += s[j];
        }
        lsum += __shfl_xor_sync(FULL, lsum, 1);
        lsum += __shfl_xor_sync(FULL, lsum, 2);
        l = l * alpha + lsum;
        m = mnew;
#pragma unroll
        for (int i = 0; i < 16; i++) o[i] *= alpha;

        // ---- O += P V ----
#pragma unroll 1
        for (int csrc = 0; csrc < 4; csrc++) {
#pragma unroll
            for (int i = 0; i < 16; i++) {
                const float pv = __shfl_sync(FULL, s[i], base + csrc);
                const int tok = csrc * 16 + i;
#pragma unroll
                for (int i4 = 0; i4 < 4; i4++) {
                    float4 vv = *(const float4*)(&Vs[tok][i4 * 16 + c * 4]);
                    o[i4 * 4 + 0] = fmaf(pv, vv.x, o[i4 * 4 + 0]);
                    o[i4 * 4 + 1] = fmaf(pv, vv.y, o[i4 * 4 + 1]);
                    o[i4 * 4 + 2] = fmaf(pv, vv.z, o[i4 * 4 + 2]);
                    o[i4 * 4 + 3] = fmaf(pv, vv.w, o[i4 * 4 + 3]);
                }
            }
        }
    }

    // ---- finalize: divide by row sum and store (dims d = i4*16 + c*4 + w) ----
    const float invl = 1.f / l;
    float* op = out + ((size_t)b * TSEQ + (size_t)qt * 64 + r) * HS;
#pragma unroll
    for (int i4 = 0; i4 < 4; i4++) {
        float4 t;
        t.x = o[i4 * 4 + 0] * invl;
        t.y = o[i4 * 4 + 1] * invl;
        t.z = o[i4 * 4 + 2] * invl;
        t.w = o[i4 * 4 + 3] * invl;
        *(float4*)(op + i4 * 16 + c * 4) = t;
    }
}

// ---------------------------------------------------------------------------
extern "C" void kernel_launch(void* const* d_in, const int* in_sizes, int n_in,
                              void* d_out, int out_size)
{
    const float* x  = (const float*)d_in[0];
    const float* Wq = (const float*)d_in[1];
    const float* Wk = (const float*)d_in[2];
    const float* Wv = (const float*)d_in[3];
    float* out = (float*)d_out;

    proj_kernel<<<512, 256>>>(x, Wq, Wk, Wv);
    attn_kernel<<<dim3(64, BATCH), 256>>>(out);
}

// round 2
// speedup vs baseline: 3.3959x; 3.3959x over previous
#include <cuda_runtime.h>
#include <math.h>

#define BATCH 4
#define TSEQ  4096
#define EMB   100
#define HS    64
#define NQT   64      // 64-row q tiles per batch
#define CH    8       // k-tiles per chunk (split-K granularity)
#define MAXCH 8
#define ITEMS_PER_B 288   // sum over g=0..7 of 8*(g+1)

// Scratch (static device arrays: allocation-free per harness rules)
__device__ float g_q[BATCH * TSEQ * HS];
__device__ float g_k[BATCH * TSEQ * HS];
__device__ float g_v[BATCH * TSEQ * HS];
__device__ float g_part[BATCH][NQT][MAXCH][64][HS];  // unnormalized O partials
__device__ float g_ml[BATCH][NQT][MAXCH][64][2];     // (m, l) per row per chunk

// ---------------------------------------------------------------------------
// Kernel 1: fused Q/K/V projection (unchanged from round 1; ~27us, not binding)
// ---------------------------------------------------------------------------
__global__ __launch_bounds__(256) void proj_kernel(
    const float* __restrict__ x,
    const float* __restrict__ Wq,
    const float* __restrict__ Wk,
    const float* __restrict__ Wv)
{
    __shared__ float xs[32][EMB];
    const int tid = threadIdx.x;
    const int row0 = blockIdx.x * 32;

    for (int i = tid; i < 32 * EMB; i += 256)
        xs[i / EMB][i % EMB] = x[row0 * EMB + i];
    __syncthreads();

    const int j  = tid & 63;
    const int rg = tid >> 6;

    float q[8], k[8], v[8];
#pragma unroll
    for (int rr = 0; rr < 8; rr++) { q[rr] = 0.f; k[rr] = 0.f; v[rr] = 0.f; }

    for (int e = 0; e < EMB; e++) {
        const float wq = __ldg(&Wq[e * HS + j]);
        const float wk = __ldg(&Wk[e * HS + j]);
        const float wv = __ldg(&Wv[e * HS + j]);
#pragma unroll
        for (int rr = 0; rr < 8; rr++) {
            const float xv = xs[rg * 8 + rr][e];
            q[rr] = fmaf(xv, wq, q[rr]);
            k[rr] = fmaf(xv, wk, k[rr]);
            v[rr] = fmaf(xv, wv, v[rr]);
        }
    }

#pragma unroll
    for (int rr = 0; rr < 8; rr++) {
        const int row = row0 + rg * 8 + rr;
        g_q[row * HS + j] = q[rr];
        g_k[row * HS + j] = k[rr];
        g_v[row * HS + j] = v[rr];
    }
}

// ---------------------------------------------------------------------------
// Kernel 2: split-K causal flash attention, 4x4 register-blocked.
// Work item: (b, qt, chunk). chunk = up to CH k-tiles of 64 tokens.
// 256 threads: ty = tid>>4 owns rows 4ty..4ty+3; tx = tid&15 owns
// score cols / output dims 4tx..4tx+3. FMA:LDS.128 ratio = 8:1.
// ---------------------------------------------------------------------------
__global__ __launch_bounds__(256, 3) void attn_kernel()
{
    // ---- decode blockIdx -> (b, qt, ch) ----
    const int b = blockIdx.x / ITEMS_PER_B;
    const int i = blockIdx.x % ITEMS_PER_B;
    int g = 0;
    while (4 * (g + 1) * (g + 2) <= i) g++;     // group g: qt in [8g, 8g+7], g+1 chunks
    const int off = i - 4 * g * (g + 1);
    const int qt = 8 * g + off / (g + 1);
    const int ch = off % (g + 1);
    const int k0 = ch * CH;
    const int k1 = min(k0 + CH, qt + 1);

    __shared__ float Qs[64][64];
    __shared__ float Ks[64][64];   // XOR chunk-swizzled
    __shared__ float Vs[64][64];
    __shared__ float Ps[64][64];

    const int tid = threadIdx.x;
    const int ty = tid >> 4;       // 0..15
    const int tx = tid & 15;       // 0..15
    const unsigned FULL = 0xffffffffu;

    // ---- load Q tile (scaled by 1/sqrt(64)) ----
    const float* qp = g_q + ((size_t)b * TSEQ + (size_t)qt * 64) * HS;
#pragma unroll
    for (int it = 0; it < 4; it++) {
        const int idx = tid + it * 256;
        const int row = idx >> 4, c4 = idx & 15;
        float4 t = *(const float4*)(qp + row * HS + c4 * 4);
        t.x *= 0.125f; t.y *= 0.125f; t.z *= 0.125f; t.w *= 0.125f;
        *(float4*)(&Qs[row][c4 * 4]) = t;
    }

    float m[4], l[4];
    float4 o4[4];
#pragma unroll
    for (int ii = 0; ii < 4; ii++) {
        m[ii] = -INFINITY; l[ii] = 0.f;
        o4[ii] = make_float4(0.f, 0.f, 0.f, 0.f);
    }

    const float* kp0 = g_k + (size_t)b * TSEQ * HS;
    const float* vp0 = g_v + (size_t)b * TSEQ * HS;

    for (int kt = k0; kt < k1; kt++) {
        __syncthreads();   // prev PV reads of Vs/Ps done
        const float* kp = kp0 + (size_t)kt * 64 * HS;
        const float* vp = vp0 + (size_t)kt * 64 * HS;
#pragma unroll
        for (int it = 0; it < 4; it++) {
            const int idx = tid + it * 256;
            const int row = idx >> 4, c4 = idx & 15;
            float4 kv = *(const float4*)(kp + row * HS + c4 * 4);
            *(float4*)(&Ks[row][((c4 ^ (row >> 2)) & 15) * 4]) = kv;
            float4 vv = *(const float4*)(vp + row * HS + c4 * 4);
            *(float4*)(&Vs[row][c4 * 4]) = vv;
        }
        __syncthreads();

        // ---- S(4x4) = Q K^T ----
        float s[4][4];
#pragma unroll
        for (int ii = 0; ii < 4; ii++)
#pragma unroll
            for (int j = 0; j < 4; j++) s[ii][j] = 0.f;

#pragma unroll
        for (int kc = 0; kc < 16; kc++) {
            float4 kv[4];
#pragma unroll
            for (int j = 0; j < 4; j++)    // row 4tx+j, k-chunk kc stored at kc^tx
                kv[j] = *(const float4*)(&Ks[4 * tx + j][((kc ^ tx) & 15) * 4]);
#pragma unroll
            for (int ii = 0; ii < 4; ii++) {
                const float4 qv = *(const float4*)(&Qs[4 * ty + ii][kc * 4]);
#pragma unroll
                for (int j = 0; j < 4; j++) {
                    s[ii][j] = fmaf(qv.x, kv[j].x, s[ii][j]);
                    s[ii][j] = fmaf(qv.y, kv[j].y, s[ii][j]);
                    s[ii][j] = fmaf(qv.z, kv[j].z, s[ii][j]);
                    s[ii][j] = fmaf(qv.w, kv[j].w, s[ii][j]);
                }
            }
        }

        // ---- causal mask on the diagonal tile ----
        if (kt == qt) {
#pragma unroll
            for (int ii = 0; ii < 4; ii++)
#pragma unroll
                for (int j = 0; j < 4; j++)
                    if (4 * tx + j > 4 * ty + ii) s[ii][j] = -INFINITY;
        }

        // ---- online softmax per row (reduce across 16 tx lanes) ----
#pragma unroll
        for (int ii = 0; ii < 4; ii++) {
            float tm = fmaxf(fmaxf(s[ii][0], s[ii][1]), fmaxf(s[ii][2], s[ii][3]));
            tm = fmaxf(tm, __shfl_xor_sync(FULL, tm, 1));
            tm = fmaxf(tm, __shfl_xor_sync(FULL, tm, 2));
            tm = fmaxf(tm, __shfl_xor_sync(FULL, tm, 4));
            tm = fmaxf(tm, __shfl_xor_sync(FULL, tm, 8));
            const float mn = fmaxf(m[ii], tm);
            const float al = __expf(m[ii] - mn);
            float ls = 0.f;
#pragma unroll
            for (int j = 0; j < 4; j++) {
                s[ii][j] = __expf(s[ii][j] - mn);
                ls += s[ii][j];
            }
            ls += __shfl_xor_sync(FULL, ls, 1);
            ls += __shfl_xor_sync(FULL, ls, 2);
            ls += __shfl_xor_sync(FULL, ls, 4);
            ls += __shfl_xor_sync(FULL, ls, 8);
            l[ii] = l[ii] * al + ls;
            m[ii] = mn;
            o4[ii].x *= al; o4[ii].y *= al; o4[ii].z *= al; o4[ii].w *= al;
            *(float4*)(&Ps[4 * ty + ii][4 * tx]) =
                make_float4(s[ii][0], s[ii][1], s[ii][2], s[ii][3]);
        }
        __syncthreads();   // all of P visible

        // ---- O(4x4) += P V ----
#pragma unroll
        for (int tc = 0; tc < 16; tc++) {
            float4 vv[4];
#pragma unroll
            for (int j = 0; j < 4; j++)
                vv[j] = *(const float4*)(&Vs[4 * tc + j][4 * tx]);
#pragma unroll
            for (int ii = 0; ii < 4; ii++) {
                const float4 pv = *(const float4*)(&Ps[4 * ty + ii][4 * tc]);
                o4[ii].x = fmaf(pv.x, vv[0].x, o4[ii].x);
                o4[ii].y = fmaf(pv.x, vv[0].y, o4[ii].y);
                o4[ii].z = fmaf(pv.x, vv[0].z, o4[ii].z);
                o4[ii].w = fmaf(pv.x, vv[0].w, o4[ii].w);
                o4[ii].x = fmaf(pv.y, vv[1].x, o4[ii].x);
                o4[ii].y = fmaf(pv.y, vv[1].y, o4[ii].y);
                o4[ii].z = fmaf(pv.y, vv[1].z, o4[ii].z);
                o4[ii].w = fmaf(pv.y, vv[1].w, o4[ii].w);
                o4[ii].x = fmaf(pv.z, vv[2].x, o4[ii].x);
                o4[ii].y = fmaf(pv.z, vv[2].y, o4[ii].y);
                o4[ii].z = fmaf(pv.z, vv[2].z, o4[ii].z);
                o4[ii].w = fmaf(pv.z, vv[2].w, o4[ii].w);
                o4[ii].x = fmaf(pv.w, vv[3].x, o4[ii].x);
                o4[ii].y = fmaf(pv.w, vv[3].y, o4[ii].y);
                o4[ii].z = fmaf(pv.w, vv[3].z, o4[ii].z);
                o4[ii].w = fmaf(pv.w, vv[3].w, o4[ii].w);
            }
        }
    }

    // ---- store unnormalized partials + (m, l) ----
#pragma unroll
    for (int ii = 0; ii < 4; ii++) {
        *(float4*)(&g_part[b][qt][ch][4 * ty + ii][4 * tx]) = o4[ii];
        if (tx == 0) {
            g_ml[b][qt][ch][4 * ty + ii][0] = m[ii];
            g_ml[b][qt][ch][4 * ty + ii][1] = l[ii];
        }
    }
}

// ---------------------------------------------------------------------------
// Kernel 3: merge split-K partials.  Grid 256 = (b,qt); 256 threads:
// thread -> (row = tid>>2, 16 dims at (tid&3)*16).
// ---------------------------------------------------------------------------
__global__ __launch_bounds__(256) void merge_kernel(float* __restrict__ out)
{
    const int b  = blockIdx.x >> 6;
    const int qt = blockIdx.x & 63;
    const int nch = (qt >> 3) + 1;
    const int tid = threadIdx.x;
    const int row = tid >> 2;
    const int dp  = tid & 3;

    float M = -INFINITY;
    for (int c = 0; c < nch; c++)
        M = fmaxf(M, g_ml[b][qt][c][row][0]);

    float L = 0.f;
    float acc[16];
#pragma unroll
    for (int q = 0; q < 16; q++) acc[q] = 0.f;

    for (int c = 0; c < nch; c++) {
        const float w = __expf(g_ml[b][qt][c][row][0] - M);
        L += g_ml[b][qt][c][row][1] * w;
#pragma unroll
        for (int q4 = 0; q4 < 4; q4++) {
            float4 p = *(const float4*)(&g_part[b][qt][c][row][dp * 16 + q4 * 4]);
            acc[q4 * 4 + 0] = fmaf(p.x, w, acc[q4 * 4 + 0]);
            acc[q4 * 4 + 1] = fmaf(p.y, w, acc[q4 * 4 + 1]);
            acc[q4 * 4 + 2] = fmaf(p.z, w, acc[q4 * 4 + 2]);
            acc[q4 * 4 + 3] = fmaf(p.w, w, acc[q4 * 4 + 3]);
        }
    }

    const float inv = 1.f / L;
    float* op = out + ((size_t)b * TSEQ + (size_t)qt * 64 + row) * HS + dp * 16;
#pragma unroll
    for (int q4 = 0; q4 < 4; q4++) {
        float4 t;
        t.x = acc[q4 * 4 + 0] * inv;
        t.y = acc[q4 * 4 + 1] * inv;
        t.z = acc[q4 * 4 + 2] * inv;
        t.w = acc[q4 * 4 + 3] * inv;
        *(float4*)(op + q4 * 4) = t;
    }
}

// ---------------------------------------------------------------------------
extern "C" void kernel_launch(void* const* d_in, const int* in_sizes, int n_in,
                              void* d_out, int out_size)
{
    const float* x  = (const float*)d_in[0];
    const float* Wq = (const float*)d_in[1];
    const float* Wk = (const float*)d_in[2];
    const float* Wv = (const float*)d_in[3];
    float* out = (float*)d_out;

    proj_kernel<<<512, 256>>>(x, Wq, Wk, Wv);
    attn_kernel<<<BATCH * ITEMS_PER_B, 256>>>();
    merge_kernel<<<BATCH * NQT, 256>>>(out);
}

// round 5
// speedup vs baseline: 7.0956x; 2.0894x over previous
#include <cuda_runtime.h>
#include <cuda_bf16.h>
#include <cstdint>
#include <math.h>

#define BATCH 4
#define TSEQ  4096
#define EMB   100
#define HS    64
#define NQT   32            // 128-row q tiles per batch
#define MAXCH 8
#define ITEMS_PER_B 144     // sum over qt of ceil((qt+1)/4)

// ---------------- global scratch (bf16 hi/lo splits, 16B aligned) ----------
__device__ __align__(16) __nv_bfloat16 g_qh[BATCH * TSEQ * HS];
__device__ __align__(16) __nv_bfloat16 g_ql[BATCH * TSEQ * HS];
__device__ __align__(16) __nv_bfloat16 g_kh[BATCH * TSEQ * HS];
__device__ __align__(16) __nv_bfloat16 g_kl[BATCH * TSEQ * HS];
__device__ __align__(16) __nv_bfloat16 g_vth[BATCH * 64 * HS * 64]; // [ktile][dim][tok]
__device__ __align__(16) __nv_bfloat16 g_vtl[BATCH * 64 * HS * 64];
__device__ float g_part[BATCH * NQT * MAXCH * 128 * HS];  // unnormalized O
__device__ float g_l[BATCH * NQT * MAXCH * 128];          // row sums

// ---------------- PTX helpers (all arch-portable: sm_80-era) ---------------
__device__ __forceinline__ uint32_t smem_u32(const void* p) {
    uint32_t a;
    asm("{ .reg .u64 t; cvta.to.shared.u64 t, %1; cvt.u32.u64 %0, t; }" : "=r"(a) : "l"(p));
    return a;
}
__device__ __forceinline__ void cpa16(uint32_t dst, const void* src) {
    asm volatile("cp.async.cg.shared.global [%0], [%1], 16;" :: "r"(dst), "l"(src));
}
__device__ __forceinline__ void cpa_commit() { asm volatile("cp.async.commit_group;" ::: "memory"); }
__device__ __forceinline__ void cpa_wait1()  { asm volatile("cp.async.wait_group 1;" ::: "memory"); }
__device__ __forceinline__ void ldsm4(uint32_t* r, uint32_t addr) {
    asm volatile("ldmatrix.sync.aligned.m8n8.x4.shared.b16 {%0,%1,%2,%3}, [%4];"
        : "=r"(r[0]), "=r"(r[1]), "=r"(r[2]), "=r"(r[3]) : "r"(addr));
}
__device__ __forceinline__ void mma16816(float* c, const uint32_t* a, uint32_t b0, uint32_t b1) {
    asm volatile("mma.sync.aligned.m16n8k16.row.col.f32.bf16.bf16.f32 "
        "{%0,%1,%2,%3}, {%4,%5,%6,%7}, {%8,%9}, {%0,%1,%2,%3};"
        : "+f"(c[0]), "+f"(c[1]), "+f"(c[2]), "+f"(c[3])
        : "r"(a[0]), "r"(a[1]), "r"(a[2]), "r"(a[3]), "r"(b0), "r"(b1));
}

// SMEM layout: per part two 8KB buffers
#define OFF_KH 0
#define OFF_KL 16384
#define OFF_VH 32768
#define OFF_VL 49152
#define SMEM_TOTAL 65536

// ---------------------------------------------------------------------------
// Kernel 1: fused Q/K/V projection -> bf16 hi/lo splits (V transposed per tile)
// ---------------------------------------------------------------------------
__global__ __launch_bounds__(256) void proj_kernel(
    const float* __restrict__ x, const float* __restrict__ Wq,
    const float* __restrict__ Wk, const float* __restrict__ Wv)
{
    __shared__ float xs[32][EMB];
    const int tid = threadIdx.x;
    const int row0 = blockIdx.x * 32;

    for (int i = tid; i < 32 * EMB; i += 256)
        xs[i / EMB][i % EMB] = x[row0 * EMB + i];
    __syncthreads();

    const int j  = tid & 63;
    const int rg = tid >> 6;

    float q[8], k[8], v[8];
#pragma unroll
    for (int rr = 0; rr < 8; rr++) { q[rr] = 0.f; k[rr] = 0.f; v[rr] = 0.f; }

    for (int e = 0; e < EMB; e++) {
        const float wq = __ldg(&Wq[e * HS + j]);
        const float wk = __ldg(&Wk[e * HS + j]);
        const float wv = __ldg(&Wv[e * HS + j]);
#pragma unroll
        for (int rr = 0; rr < 8; rr++) {
            const float xv = xs[rg * 8 + rr][e];
            q[rr] = fmaf(xv, wq, q[rr]);
            k[rr] = fmaf(xv, wk, k[rr]);
            v[rr] = fmaf(xv, wv, v[rr]);
        }
    }

    union { __nv_bfloat16 h[8]; uint4 u; } vh, vl;
#pragma unroll
    for (int rr = 0; rr < 8; rr++) {
        const int row = row0 + rg * 8 + rr;
        const float qs = q[rr] * 0.125f;   // fold 1/sqrt(64)
        __nv_bfloat16 qh = __float2bfloat16(qs);
        g_qh[row * HS + j] = qh;
        g_ql[row * HS + j] = __float2bfloat16(qs - __bfloat162float(qh));
        __nv_bfloat16 kh = __float2bfloat16(k[rr]);
        g_kh[row * HS + j] = kh;
        g_kl[row * HS + j] = __float2bfloat16(k[rr] - __bfloat162float(kh));
        __nv_bfloat16 vh1 = __float2bfloat16(v[rr]);
        vh.h[rr] = vh1;
        vl.h[rr] = __float2bfloat16(v[rr] - __bfloat162float(vh1));
    }
    const int kt   = (row0 + rg * 8) / 64;     // global 64-token tile (incl. batch)
    const int tok0 = (row0 + rg * 8) % 64;
    *(uint4*)(&g_vth[kt * (HS * 64) + j * 64 + tok0]) = vh.u;
    *(uint4*)(&g_vtl[kt * (HS * 64) + j * 64 + tok0]) = vl.u;
}

// ---------------------------------------------------------------------------
// Kernel 2: mma.sync split-K causal flash attention (fixed m=0, P in registers)
// ---------------------------------------------------------------------------
__device__ __forceinline__ void issue_tile(uint32_t sb, int tid, int buf,
                                           int b, int ktile)
{
    const char* kh = (const char*)g_kh + (size_t)(b * TSEQ + ktile * 64) * HS * 2;
    const char* kl = (const char*)g_kl + (size_t)(b * TSEQ + ktile * 64) * HS * 2;
    const char* vh = (const char*)g_vth + (size_t)(b * 64 + ktile) * (HS * 64) * 2;
    const char* vl = (const char*)g_vtl + (size_t)(b * 64 + ktile) * (HS * 64) * 2;
#pragma unroll
    for (int rep = 0; rep < 2; rep++) {
        const int idx = tid + rep * 256;     // 16B chunk index 0..511
        const int row = idx >> 3, c = idx & 7;
        const int dsw = row * 128 + ((c ^ (row & 7)) * 16);
        const int ssw = row * 128 + c * 16;
        cpa16(sb + OFF_KH + buf * 8192 + dsw, kh + ssw);
        cpa16(sb + OFF_KL + buf * 8192 + dsw, kl + ssw);
        cpa16(sb + OFF_VH + buf * 8192 + dsw, vh + ssw);
        cpa16(sb + OFF_VL + buf * 8192 + dsw, vl + ssw);
    }
}

__global__ __launch_bounds__(256, 1) void attn_kernel()
{
    extern __shared__ char sm[];
    const uint32_t sb = smem_u32(sm);
    const int tid  = threadIdx.x;
    const int w    = tid >> 5;
    const int lane = tid & 31;
    const int gid  = lane >> 2;   // 0..7
    const int tig  = lane & 3;    // 0..3
    const unsigned FULL = 0xffffffffu;

    // ---- decode blockIdx (heavy items first) ----
    const int b = blockIdx.x & 3;
    const int i = 143 - (int)(blockIdx.x >> 2);
    int g = 1;
    while (i >= 2 * g * (g + 1)) g++;            // 2g(g-1) <= i < 2g(g+1)
    const int off = i - 2 * g * (g - 1);
    const int qt = 4 * (g - 1) + off / g;
    const int ch = off % g;
    const int k0t = ch * 8;                       // first 64-token k-tile
    const int n = min(k0t + 8, 2 * qt + 2) - k0t; // tiles in this chunk (always >=2)

    // ---- Q A-fragments (hi/lo), loaded directly from global ----
    uint32_t qh[4][4], ql[4][4];
    {
        const __nv_bfloat16* qbh = g_qh + (size_t)(b * TSEQ + qt * 128 + w * 16) * HS;
        const __nv_bfloat16* qbl = g_ql + (size_t)(b * TSEQ + qt * 128 + w * 16) * HS;
#pragma unroll
        for (int kk = 0; kk < 4; kk++) {
            const int cA = kk * 16 + tig * 2;
            qh[kk][0] = *(const uint32_t*)(qbh + gid * HS + cA);
            qh[kk][1] = *(const uint32_t*)(qbh + (gid + 8) * HS + cA);
            qh[kk][2] = *(const uint32_t*)(qbh + gid * HS + cA + 8);
            qh[kk][3] = *(const uint32_t*)(qbh + (gid + 8) * HS + cA + 8);
            ql[kk][0] = *(const uint32_t*)(qbl + gid * HS + cA);
            ql[kk][1] = *(const uint32_t*)(qbl + (gid + 8) * HS + cA);
            ql[kk][2] = *(const uint32_t*)(qbl + gid * HS + cA + 8);
            ql[kk][3] = *(const uint32_t*)(qbl + (gid + 8) * HS + cA + 8);
        }
    }

    float oacc[8][4];
#pragma unroll
    for (int j = 0; j < 8; j++)
#pragma unroll
        for (int q = 0; q < 4; q++) oacc[j][q] = 0.f;
    float lsumA = 0.f, lsumB = 0.f;
    const int growA = qt * 128 + w * 16 + gid;
    const int growB = growA + 8;

    // ldmatrix per-lane address components (group = lane>>3, i = lane&7)
    const int lgrp = lane >> 3, li = lane & 7;
    const int rsel = (lgrp >> 1) * 8 + li;   // row-within-16 selector
    const int csel = lgrp & 1;               // chunk half selector

    // prologue
    issue_tile(sb, tid, 0, b, k0t);
    cpa_commit();

    for (int t = 0; t < n; t++) {
        const int buf = t & 1;
        if (t + 1 < n) issue_tile(sb, tid, buf ^ 1, b, k0t + t + 1);
        cpa_commit();
        cpa_wait1();
        __syncthreads();

        const uint32_t kbase  = sb + OFF_KH + buf * 8192;
        const uint32_t klbase = sb + OFF_KL + buf * 8192;
        const uint32_t vbase  = sb + OFF_VH + buf * 8192;
        const uint32_t vlbase = sb + OFF_VL + buf * 8192;

        // ---- S = Q K^T (3-term split) ----
        float sacc[8][4];
#pragma unroll
        for (int j = 0; j < 8; j++)
#pragma unroll
            for (int q = 0; q < 4; q++) sacc[j][q] = 0.f;

#pragma unroll
        for (int kk = 0; kk < 4; kk++) {
#pragma unroll
            for (int jp = 0; jp < 4; jp++) {
                const int tok = jp * 16 + rsel;
                const int c = kk * 2 + csel;
                const uint32_t a = tok * 128 + ((c ^ (tok & 7)) * 16);
                uint32_t bh[4], bl[4];
                ldsm4(bh, kbase + a);
                ldsm4(bl, klbase + a);
                mma16816(sacc[2 * jp],     qh[kk], bh[0], bh[1]);
                mma16816(sacc[2 * jp],     ql[kk], bh[0], bh[1]);
                mma16816(sacc[2 * jp],     qh[kk], bl[0], bl[1]);
                mma16816(sacc[2 * jp + 1], qh[kk], bh[2], bh[3]);
                mma16816(sacc[2 * jp + 1], ql[kk], bh[2], bh[3]);
                mma16816(sacc[2 * jp + 1], qh[kk], bl[2], bl[3]);
            }
        }

        // ---- epilogue: mask + exp + row-sum + bf16 split (P stays in regs) ----
        uint32_t ph[4][4], pl[4][4];
#pragma unroll
        for (int j = 0; j < 8; j++) {
            const int tok0 = (k0t + t) * 64 + j * 8 + tig * 2;
            float p0 = (tok0     <= growA) ? __expf(sacc[j][0]) : 0.f;
            float p1 = (tok0 + 1 <= growA) ? __expf(sacc[j][1]) : 0.f;
            float p2 = (tok0     <= growB) ? __expf(sacc[j][2]) : 0.f;
            float p3 = (tok0 + 1 <= growB) ? __expf(sacc[j][3]) : 0.f;
            lsumA += p0 + p1;
            lsumB += p2 + p3;
            __nv_bfloat162 hA = __floats2bfloat162_rn(p0, p1);
            __nv_bfloat162 hB = __floats2bfloat162_rn(p2, p3);
            float2 fA = __bfloat1622float2(hA);
            float2 fB = __bfloat1622float2(hB);
            __nv_bfloat162 lA = __floats2bfloat162_rn(p0 - fA.x, p1 - fA.y);
            __nv_bfloat162 lB = __floats2bfloat162_rn(p2 - fB.x, p3 - fB.y);
            const int kt = j >> 1, hi = (j & 1) * 2;
            ph[kt][hi]     = *(uint32_t*)&hA;
            ph[kt][hi + 1] = *(uint32_t*)&hB;
            pl[kt][hi]     = *(uint32_t*)&lA;
            pl[kt][hi + 1] = *(uint32_t*)&lB;
        }

        // ---- O += P V (3-term split) ----
#pragma unroll
        for (int kt = 0; kt < 4; kt++) {
#pragma unroll
            for (int jdp = 0; jdp < 4; jdp++) {
                const int dim = jdp * 16 + rsel;
                const int c = kt * 2 + csel;
                const uint32_t a = dim * 128 + ((c ^ (dim & 7)) * 16);
                uint32_t vh[4], vl[4];
                ldsm4(vh, vbase + a);
                ldsm4(vl, vlbase + a);
                mma16816(oacc[2 * jdp],     ph[kt], vh[0], vh[1]);
                mma16816(oacc[2 * jdp],     pl[kt], vh[0], vh[1]);
                mma16816(oacc[2 * jdp],     ph[kt], vl[0], vl[1]);
                mma16816(oacc[2 * jdp + 1], ph[kt], vh[2], vh[3]);
                mma16816(oacc[2 * jdp + 1], pl[kt], vh[2], vh[3]);
                mma16816(oacc[2 * jdp + 1], ph[kt], vl[2], vl[3]);
            }
        }
        __syncthreads();   // all reads of this buffer done before it is refilled
    }

    // ---- FIX (R4 post-mortem): reduce row sums across the 4-lane quad ----
    lsumA += __shfl_xor_sync(FULL, lsumA, 1);
    lsumA += __shfl_xor_sync(FULL, lsumA, 2);
    lsumB += __shfl_xor_sync(FULL, lsumB, 1);
    lsumB += __shfl_xor_sync(FULL, lsumB, 2);

    // ---- store partials ----
    const size_t pbase = (((size_t)(b * NQT + qt) * MAXCH + ch) * 128) * HS;
    const int rowA = w * 16 + gid;
#pragma unroll
    for (int jd = 0; jd < 8; jd++) {
        const int col = jd * 8 + tig * 2;
        *(float2*)(&g_part[pbase + (size_t)rowA * HS + col]) =
            make_float2(oacc[jd][0], oacc[jd][1]);
        *(float2*)(&g_part[pbase + (size_t)(rowA + 8) * HS + col]) =
            make_float2(oacc[jd][2], oacc[jd][3]);
    }
    if (tig == 0) {
        const size_t lbase = (((size_t)(b * NQT + qt) * MAXCH + ch) * 128);
        g_l[lbase + rowA] = lsumA;
        g_l[lbase + rowA + 8] = lsumB;
    }
}

// ---------------------------------------------------------------------------
// Kernel 3: merge split-K partials (fixed m=0 -> plain sums)
// ---------------------------------------------------------------------------
__global__ __launch_bounds__(256) void merge_kernel(float* __restrict__ out)
{
    const int b  = blockIdx.x >> 5;
    const int qt = blockIdx.x & 31;
    const int nch = qt / 4 + 1;
    const int tid = threadIdx.x;
    const int row = tid >> 1;
    const int d0  = (tid & 1) * 32;

    float acc[32];
#pragma unroll
    for (int q = 0; q < 32; q++) acc[q] = 0.f;
    float L = 0.f;

    for (int c = 0; c < nch; c++) {
        L += g_l[(((size_t)(b * NQT + qt) * MAXCH + c) * 128) + row];
        const size_t pb = ((((size_t)(b * NQT + qt) * MAXCH + c) * 128) + row) * HS + d0;
#pragma unroll
        for (int q = 0; q < 8; q++) {
            float4 v = *(const float4*)(&g_part[pb + 4 * q]);
            acc[4*q]   += v.x; acc[4*q+1] += v.y;
            acc[4*q+2] += v.z; acc[4*q+3] += v.w;
        }
    }
    const float inv = 1.f / L;
    float* op = out + ((size_t)b * TSEQ + qt * 128 + row) * HS + d0;
#pragma unroll
    for (int q = 0; q < 8; q++) {
        float4 v = make_float4(acc[4*q] * inv, acc[4*q+1] * inv,
                               acc[4*q+2] * inv, acc[4*q+3] * inv);
        *(float4*)(op + 4 * q) = v;
    }
}

// ---------------------------------------------------------------------------
extern "C" void kernel_launch(void* const* d_in, const int* in_sizes, int n_in,
                              void* d_out, int out_size)
{
    const float* x  = (const float*)d_in[0];
    const float* Wq = (const float*)d_in[1];
    const float* Wk = (const float*)d_in[2];
    const float* Wv = (const float*)d_in[3];
    float* out = (float*)d_out;

    cudaFuncSetAttribute(attn_kernel, cudaFuncAttributeMaxDynamicSharedMemorySize, SMEM_TOTAL);

    proj_kernel<<<512, 256>>>(x, Wq, Wk, Wv);
    attn_kernel<<<BATCH * ITEMS_PER_B, 256, SMEM_TOTAL>>>();
    merge_kernel<<<BATCH * NQT, 256>>>(out);
}

// round 6
// speedup vs baseline: 12.1855x; 1.7173x over previous
#include <cuda_runtime.h>
#include <cuda_fp16.h>
#include <cstdint>
#include <math.h>

#define BATCH 4
#define TSEQ  4096
#define EMB   100
#define HS    64
#define NQT   32            // 128-row q tiles per batch
#define MAXCH 8
#define ITEMS_PER_B 144     // sum over qt of ceil((qt+1)/4)

// ---------------- global scratch ----------------
__device__ __align__(16) __half g_q[BATCH * TSEQ * HS];          // q/8, fp16
__device__ __align__(16) __half g_k[BATCH * TSEQ * HS];          // fp16
__device__ __align__(16) __half g_vt[BATCH * 64 * HS * 64];      // [ktile][dim][tok]
__device__ __align__(16) float g_wt[3 * HS * EMB];               // W^T: [mat][j][e]
__device__ float g_part[BATCH * NQT * MAXCH * 128 * HS];         // unnormalized O
__device__ float g_l[BATCH * NQT * MAXCH * 128];                 // row sums

// ---------------- PTX helpers (arch-portable, sm_80-era) ---------------
__device__ __forceinline__ uint32_t smem_u32(const void* p) {
    uint32_t a;
    asm("{ .reg .u64 t; cvta.to.shared.u64 t, %1; cvt.u32.u64 %0, t; }" : "=r"(a) : "l"(p));
    return a;
}
__device__ __forceinline__ void cpa16(uint32_t dst, const void* src) {
    asm volatile("cp.async.cg.shared.global [%0], [%1], 16;" :: "r"(dst), "l"(src));
}
__device__ __forceinline__ void cpa_commit() { asm volatile("cp.async.commit_group;" ::: "memory"); }
__device__ __forceinline__ void cpa_wait1()  { asm volatile("cp.async.wait_group 1;" ::: "memory"); }
__device__ __forceinline__ void ldsm4(uint32_t* r, uint32_t addr) {
    asm volatile("ldmatrix.sync.aligned.m8n8.x4.shared.b16 {%0,%1,%2,%3}, [%4];"
        : "=r"(r[0]), "=r"(r[1]), "=r"(r[2]), "=r"(r[3]) : "r"(addr));
}
__device__ __forceinline__ void mma16816(float* c, const uint32_t* a, uint32_t b0, uint32_t b1) {
    asm volatile("mma.sync.aligned.m16n8k16.row.col.f32.f16.f16.f32 "
        "{%0,%1,%2,%3}, {%4,%5,%6,%7}, {%8,%9}, {%0,%1,%2,%3};"
        : "+f"(c[0]), "+f"(c[1]), "+f"(c[2]), "+f"(c[3])
        : "r"(a[0]), "r"(a[1]), "r"(a[2]), "r"(a[3]), "r"(b0), "r"(b1));
}

// SMEM: K and V tiles, double buffered (8KB each)
#define OFF_K 0
#define OFF_V 16384
#define SMEM_TOTAL 32768

// ---------------------------------------------------------------------------
// Kernel 0: transpose W -> g_wt[mat][j][e] so proj can read W with LDG.128
// ---------------------------------------------------------------------------
__global__ void wt_kernel(const float* __restrict__ Wq,
                          const float* __restrict__ Wk,
                          const float* __restrict__ Wv)
{
    for (int i = blockIdx.x * 256 + threadIdx.x; i < HS * EMB; i += gridDim.x * 256) {
        const int j = i / EMB, e = i % EMB;
        g_wt[0 * HS * EMB + i] = Wq[e * HS + j];
        g_wt[1 * HS * EMB + i] = Wk[e * HS + j];
        g_wt[2 * HS * EMB + i] = Wv[e * HS + j];
    }
}

// ---------------------------------------------------------------------------
// Kernel 1: fused Q/K/V projection -> fp16 (V transposed per 64-token tile)
// float4 on both x (SMEM) and W^T (global) -> FMA-bound.
// ---------------------------------------------------------------------------
__global__ __launch_bounds__(256) void proj_kernel(const float* __restrict__ x)
{
    __shared__ float xs[32][EMB];   // rows are 400B = 16B-aligned
    const int tid = threadIdx.x;
    const int row0 = blockIdx.x * 32;

    for (int i = tid; i < 32 * EMB; i += 256)
        xs[i / EMB][i % EMB] = x[row0 * EMB + i];
    __syncthreads();

    const int j  = tid & 63;
    const int rg = tid >> 6;

    float q[8], k[8], v[8];
#pragma unroll
    for (int rr = 0; rr < 8; rr++) { q[rr] = 0.f; k[rr] = 0.f; v[rr] = 0.f; }

    const float4* wq4 = (const float4*)(g_wt + 0 * HS * EMB + j * EMB);
    const float4* wk4 = (const float4*)(g_wt + 1 * HS * EMB + j * EMB);
    const float4* wv4 = (const float4*)(g_wt + 2 * HS * EMB + j * EMB);

#pragma unroll
    for (int e4 = 0; e4 < EMB / 4; e4++) {
        const float4 wq = wq4[e4];
        const float4 wk = wk4[e4];
        const float4 wv = wv4[e4];
#pragma unroll
        for (int rr = 0; rr < 8; rr++) {
            const float4 xv = *(const float4*)(&xs[rg * 8 + rr][e4 * 4]);
            q[rr] = fmaf(xv.x, wq.x, q[rr]); q[rr] = fmaf(xv.y, wq.y, q[rr]);
            q[rr] = fmaf(xv.z, wq.z, q[rr]); q[rr] = fmaf(xv.w, wq.w, q[rr]);
            k[rr] = fmaf(xv.x, wk.x, k[rr]); k[rr] = fmaf(xv.y, wk.y, k[rr]);
            k[rr] = fmaf(xv.z, wk.z, k[rr]); k[rr] = fmaf(xv.w, wk.w, k[rr]);
            v[rr] = fmaf(xv.x, wv.x, v[rr]); v[rr] = fmaf(xv.y, wv.y, v[rr]);
            v[rr] = fmaf(xv.z, wv.z, v[rr]); v[rr] = fmaf(xv.w, wv.w, v[rr]);
        }
    }

    union { __half h[8]; uint4 u; } vt;
#pragma unroll
    for (int rr = 0; rr < 8; rr++) {
        const int row = row0 + rg * 8 + rr;
        g_q[row * HS + j] = __float2half_rn(q[rr] * 0.125f);   // fold 1/sqrt(64)
        g_k[row * HS + j] = __float2half_rn(k[rr]);
        vt.h[rr] = __float2half_rn(v[rr]);
    }
    const int kt   = (row0 + rg * 8) / 64;     // global 64-token tile (incl. batch)
    const int tok0 = (row0 + rg * 8) % 64;
    *(uint4*)(&g_vt[kt * (HS * 64) + j * 64 + tok0]) = vt.u;
}

// ---------------------------------------------------------------------------
// Kernel 2: mma.sync fp16 split-K causal flash attention (m=0, P in registers)
// ---------------------------------------------------------------------------
__device__ __forceinline__ void issue_tile(uint32_t sb, int tid, int buf,
                                           int b, int ktile)
{
    const char* kp = (const char*)g_k + (size_t)(b * TSEQ + ktile * 64) * HS * 2;
    const char* vp = (const char*)g_vt + (size_t)(b * 64 + ktile) * (HS * 64) * 2;
#pragma unroll
    for (int rep = 0; rep < 2; rep++) {
        const int idx = tid + rep * 256;     // 16B chunk index 0..511
        const int row = idx >> 3, c = idx & 7;
        const int dsw = row * 128 + ((c ^ (row & 7)) * 16);
        const int ssw = row * 128 + c * 16;
        cpa16(sb + OFF_K + buf * 8192 + dsw, kp + ssw);
        cpa16(sb + OFF_V + buf * 8192 + dsw, vp + ssw);
    }
}

__global__ __launch_bounds__(256, 2) void attn_kernel()
{
    extern __shared__ char sm[];
    const uint32_t sb = smem_u32(sm);
    const int tid  = threadIdx.x;
    const int w    = tid >> 5;
    const int lane = tid & 31;
    const int gid  = lane >> 2;   // 0..7
    const int tig  = lane & 3;    // 0..3
    const unsigned FULL = 0xffffffffu;

    // ---- decode blockIdx (heavy items first) ----
    const int b = blockIdx.x & 3;
    const int i = 143 - (int)(blockIdx.x >> 2);
    int g = 1;
    while (i >= 2 * g * (g + 1)) g++;            // 2g(g-1) <= i < 2g(g+1)
    const int off = i - 2 * g * (g - 1);
    const int qt = 4 * (g - 1) + off / g;
    const int ch = off % g;
    const int k0t = ch * 8;                       // first 64-token k-tile
    const int n = min(k0t + 8, 2 * qt + 2) - k0t; // tiles in this chunk (>=2)

    // ---- Q A-fragments (fp16), loaded directly from global ----
    uint32_t qf[4][4];
    {
        const __half* qb = g_q + (size_t)(b * TSEQ + qt * 128 + w * 16) * HS;
#pragma unroll
        for (int kk = 0; kk < 4; kk++) {
            const int cA = kk * 16 + tig * 2;
            qf[kk][0] = *(const uint32_t*)(qb + gid * HS + cA);
            qf[kk][1] = *(const uint32_t*)(qb + (gid + 8) * HS + cA);
            qf[kk][2] = *(const uint32_t*)(qb + gid * HS + cA + 8);
            qf[kk][3] = *(const uint32_t*)(qb + (gid + 8) * HS + cA + 8);
        }
    }

    float oacc[8][4];
#pragma unroll
    for (int j = 0; j < 8; j++)
#pragma unroll
        for (int q = 0; q < 4; q++) oacc[j][q] = 0.f;
    float lsumA = 0.f, lsumB = 0.f;
    const int growA = qt * 128 + w * 16 + gid;
    const int growB = growA + 8;

    // ldmatrix per-lane address components
    const int lgrp = lane >> 3, li = lane & 7;
    const int rsel = (lgrp >> 1) * 8 + li;   // row-within-16 selector
    const int csel = lgrp & 1;               // chunk half selector

    issue_tile(sb, tid, 0, b, k0t);
    cpa_commit();

    for (int t = 0; t < n; t++) {
        const int buf = t & 1;
        if (t + 1 < n) issue_tile(sb, tid, buf ^ 1, b, k0t + t + 1);
        cpa_commit();
        cpa_wait1();
        __syncthreads();

        const uint32_t kbase = sb + OFF_K + buf * 8192;
        const uint32_t vbase = sb + OFF_V + buf * 8192;

        // ---- S = Q K^T ----
        float sacc[8][4];
#pragma unroll
        for (int j = 0; j < 8; j++)
#pragma unroll
            for (int q = 0; q < 4; q++) sacc[j][q] = 0.f;

#pragma unroll
        for (int kk = 0; kk < 4; kk++) {
#pragma unroll
            for (int jp = 0; jp < 4; jp++) {
                const int tok = jp * 16 + rsel;
                const int c = kk * 2 + csel;
                const uint32_t a = tok * 128 + ((c ^ (tok & 7)) * 16);
                uint32_t bh[4];
                ldsm4(bh, kbase + a);
                mma16816(sacc[2 * jp],     qf[kk], bh[0], bh[1]);
                mma16816(sacc[2 * jp + 1], qf[kk], bh[2], bh[3]);
            }
        }

        // ---- epilogue: mask + exp + row-sum + fp16 pack (P stays in regs) ----
        uint32_t pf[4][4];
#pragma unroll
        for (int j = 0; j < 8; j++) {
            const int tok0 = (k0t + t) * 64 + j * 8 + tig * 2;
            float p0 = (tok0     <= growA) ? __expf(sacc[j][0]) : 0.f;
            float p1 = (tok0 + 1 <= growA) ? __expf(sacc[j][1]) : 0.f;
            float p2 = (tok0     <= growB) ? __expf(sacc[j][2]) : 0.f;
            float p3 = (tok0 + 1 <= growB) ? __expf(sacc[j][3]) : 0.f;
            lsumA += p0 + p1;
            lsumB += p2 + p3;
            __half2 hA = __floats2half2_rn(p0, p1);
            __half2 hB = __floats2half2_rn(p2, p3);
            const int kt = j >> 1, hi = (j & 1) * 2;
            pf[kt][hi]     = *(uint32_t*)&hA;
            pf[kt][hi + 1] = *(uint32_t*)&hB;
        }

        // ---- O += P V ----
#pragma unroll
        for (int kt = 0; kt < 4; kt++) {
#pragma unroll
            for (int jdp = 0; jdp < 4; jdp++) {
                const int dim = jdp * 16 + rsel;
                const int c = kt * 2 + csel;
                const uint32_t a = dim * 128 + ((c ^ (dim & 7)) * 16);
                uint32_t vh[4];
                ldsm4(vh, vbase + a);
                mma16816(oacc[2 * jdp],     pf[kt], vh[0], vh[1]);
                mma16816(oacc[2 * jdp + 1], pf[kt], vh[2], vh[3]);
            }
        }
        __syncthreads();   // all reads of this buffer done before refill
    }

    // ---- reduce row sums across the 4-lane quad ----
    lsumA += __shfl_xor_sync(FULL, lsumA, 1);
    lsumA += __shfl_xor_sync(FULL, lsumA, 2);
    lsumB += __shfl_xor_sync(FULL, lsumB, 1);
    lsumB += __shfl_xor_sync(FULL, lsumB, 2);

    // ---- store partials ----
    const size_t pbase = (((size_t)(b * NQT + qt) * MAXCH + ch) * 128) * HS;
    const int rowA = w * 16 + gid;
#pragma unroll
    for (int jd = 0; jd < 8; jd++) {
        const int col = jd * 8 + tig * 2;
        *(float2*)(&g_part[pbase + (size_t)rowA * HS + col]) =
            make_float2(oacc[jd][0], oacc[jd][1]);
        *(float2*)(&g_part[pbase + (size_t)(rowA + 8) * HS + col]) =
            make_float2(oacc[jd][2], oacc[jd][3]);
    }
    if (tig == 0) {
        const size_t lbase = (((size_t)(b * NQT + qt) * MAXCH + ch) * 128);
        g_l[lbase + rowA] = lsumA;
        g_l[lbase + rowA + 8] = lsumB;
    }
}

// ---------------------------------------------------------------------------
// Kernel 3: merge split-K partials (fixed m=0 -> plain sums)
// ---------------------------------------------------------------------------
__global__ __launch_bounds__(256) void merge_kernel(float* __restrict__ out)
{
    const int b  = blockIdx.x >> 5;
    const int qt = blockIdx.x & 31;
    const int nch = qt / 4 + 1;
    const int tid = threadIdx.x;
    const int row = tid >> 1;
    const int d0  = (tid & 1) * 32;

    float acc[32];
#pragma unroll
    for (int q = 0; q < 32; q++) acc[q] = 0.f;
    float L = 0.f;

    for (int c = 0; c < nch; c++) {
        L += g_l[(((size_t)(b * NQT + qt) * MAXCH + c) * 128) + row];
        const size_t pb = ((((size_t)(b * NQT + qt) * MAXCH + c) * 128) + row) * HS + d0;
#pragma unroll
        for (int q = 0; q < 8; q++) {
            float4 v = *(const float4*)(&g_part[pb + 4 * q]);
            acc[4*q]   += v.x; acc[4*q+1] += v.y;
            acc[4*q+2] += v.z; acc[4*q+3] += v.w;
        }
    }
    const float inv = 1.f / L;
    float* op = out + ((size_t)b * TSEQ + qt * 128 + row) * HS + d0;
#pragma unroll
    for (int q = 0; q < 8; q++) {
        float4 v = make_float4(acc[4*q] * inv, acc[4*q+1] * inv,
                               acc[4*q+2] * inv, acc[4*q+3] * inv);
        *(float4*)(op + 4 * q) = v;
    }
}

// ---------------------------------------------------------------------------
extern "C" void kernel_launch(void* const* d_in, const int* in_sizes, int n_in,
                              void* d_out, int out_size)
{
    const float* x  = (const float*)d_in[0];
    const float* Wq = (const float*)d_in[1];
    const float* Wk = (const float*)d_in[2];
    const float* Wv = (const float*)d_in[3];
    float* out = (float*)d_out;

    cudaFuncSetAttribute(attn_kernel, cudaFuncAttributeMaxDynamicSharedMemorySize, SMEM_TOTAL);

    wt_kernel<<<25, 256>>>(Wq, Wk, Wv);
    proj_kernel<<<512, 256>>>(x);
    attn_kernel<<<BATCH * ITEMS_PER_B, 256, SMEM_TOTAL>>>();
    merge_kernel<<<BATCH * NQT, 256>>>(out);
}

// round 7
// speedup vs baseline: 13.6148x; 1.1173x over previous
#include <cuda_runtime.h>
#include <cuda_fp16.h>
#include <cstdint>
#include <math.h>

#define BATCH 4
#define TSEQ  4096
#define EMB   100
#define HS    64
#define NQT   32            // 128-row q tiles per batch
#define MAXCH 8
#define ITEMS_PER_B 144     // sum over qt of ceil((qt+1)/4)

// ---------------- global scratch ----------------
__device__ __align__(16) __half g_q[BATCH * TSEQ * HS];          // q * log2e/8, fp16
__device__ __align__(16) __half g_k[BATCH * TSEQ * HS];          // fp16
__device__ __align__(16) __half g_vt[BATCH * 64 * HS * 64];      // [ktile][dim][tok]
__device__ __align__(16) float g_wt[3 * HS * EMB];               // W^T: [mat][j][e]
__device__ float g_part[BATCH * NQT * MAXCH * 128 * HS];         // unnormalized O
__device__ float g_l[BATCH * NQT * MAXCH * 128];                 // row sums

// ---------------- PTX helpers (arch-portable, sm_80-era) ---------------
__device__ __forceinline__ uint32_t smem_u32(const void* p) {
    uint32_t a;
    asm("{ .reg .u64 t; cvta.to.shared.u64 t, %1; cvt.u32.u64 %0, t; }" : "=r"(a) : "l"(p));
    return a;
}
__device__ __forceinline__ float ex2(float x) {
    float r; asm("ex2.approx.f32 %0, %1;" : "=f"(r) : "f"(x)); return r;
}
__device__ __forceinline__ void cpa16(uint32_t dst, const void* src) {
    asm volatile("cp.async.cg.shared.global [%0], [%1], 16;" :: "r"(dst), "l"(src));
}
__device__ __forceinline__ void cpa_commit() { asm volatile("cp.async.commit_group;" ::: "memory"); }
__device__ __forceinline__ void cpa_wait1()  { asm volatile("cp.async.wait_group 1;" ::: "memory"); }
__device__ __forceinline__ void ldsm4(uint32_t* r, uint32_t addr) {
    asm volatile("ldmatrix.sync.aligned.m8n8.x4.shared.b16 {%0,%1,%2,%3}, [%4];"
        : "=r"(r[0]), "=r"(r[1]), "=r"(r[2]), "=r"(r[3]) : "r"(addr));
}
__device__ __forceinline__ void mma16816(float* c, const uint32_t* a, uint32_t b0, uint32_t b1) {
    asm volatile("mma.sync.aligned.m16n8k16.row.col.f32.f16.f16.f32 "
        "{%0,%1,%2,%3}, {%4,%5,%6,%7}, {%8,%9}, {%0,%1,%2,%3};"
        : "+f"(c[0]), "+f"(c[1]), "+f"(c[2]), "+f"(c[3])
        : "r"(a[0]), "r"(a[1]), "r"(a[2]), "r"(a[3]), "r"(b0), "r"(b1));
}

// SMEM: K and V tiles, double buffered (8KB each)
#define OFF_K 0
#define OFF_V 16384
#define SMEM_TOTAL 32768

// ---------------------------------------------------------------------------
// Kernel 0: transpose W -> g_wt[mat][j][e] so proj can read W with LDG.128
// ---------------------------------------------------------------------------
__global__ void wt_kernel(const float* __restrict__ Wq,
                          const float* __restrict__ Wk,
                          const float* __restrict__ Wv)
{
    for (int i = blockIdx.x * 256 + threadIdx.x; i < HS * EMB; i += gridDim.x * 256) {
        const int j = i / EMB, e = i % EMB;
        g_wt[0 * HS * EMB + i] = Wq[e * HS + j];
        g_wt[1 * HS * EMB + i] = Wk[e * HS + j];
        g_wt[2 * HS * EMB + i] = Wv[e * HS + j];
    }
}

// ---------------------------------------------------------------------------
// Kernel 1: fused Q/K/V projection -> fp16 (V transposed per 64-token tile)
// ---------------------------------------------------------------------------
__global__ __launch_bounds__(256) void proj_kernel(const float* __restrict__ x)
{
    __shared__ float xs[32][EMB];
    const int tid = threadIdx.x;
    const int row0 = blockIdx.x * 32;

    for (int i = tid; i < 32 * EMB; i += 256)
        xs[i / EMB][i % EMB] = x[row0 * EMB + i];
    __syncthreads();

    const int j  = tid & 63;
    const int rg = tid >> 6;

    float q[8], k[8], v[8];
#pragma unroll
    for (int rr = 0; rr < 8; rr++) { q[rr] = 0.f; k[rr] = 0.f; v[rr] = 0.f; }

    const float4* wq4 = (const float4*)(g_wt + 0 * HS * EMB + j * EMB);
    const float4* wk4 = (const float4*)(g_wt + 1 * HS * EMB + j * EMB);
    const float4* wv4 = (const float4*)(g_wt + 2 * HS * EMB + j * EMB);

#pragma unroll
    for (int e4 = 0; e4 < EMB / 4; e4++) {
        const float4 wq = wq4[e4];
        const float4 wk = wk4[e4];
        const float4 wv = wv4[e4];
#pragma unroll
        for (int rr = 0; rr < 8; rr++) {
            const float4 xv = *(const float4*)(&xs[rg * 8 + rr][e4 * 4]);
            q[rr] = fmaf(xv.x, wq.x, q[rr]); q[rr] = fmaf(xv.y, wq.y, q[rr]);
            q[rr] = fmaf(xv.z, wq.z, q[rr]); q[rr] = fmaf(xv.w, wq.w, q[rr]);
            k[rr] = fmaf(xv.x, wk.x, k[rr]); k[rr] = fmaf(xv.y, wk.y, k[rr]);
            k[rr] = fmaf(xv.z, wk.z, k[rr]); k[rr] = fmaf(xv.w, wk.w, k[rr]);
            v[rr] = fmaf(xv.x, wv.x, v[rr]); v[rr] = fmaf(xv.y, wv.y, v[rr]);
            v[rr] = fmaf(xv.z, wv.z, v[rr]); v[rr] = fmaf(xv.w, wv.w, v[rr]);
        }
    }

    // fold (1/sqrt(64)) * log2(e) into Q so attn can use raw ex2
    const float QSCALE = 0.125f * 1.4426950408889634f;
    union { __half h[8]; uint4 u; } vt;
#pragma unroll
    for (int rr = 0; rr < 8; rr++) {
        const int row = row0 + rg * 8 + rr;
        g_q[row * HS + j] = __float2half_rn(q[rr] * QSCALE);
        g_k[row * HS + j] = __float2half_rn(k[rr]);
        vt.h[rr] = __float2half_rn(v[rr]);
    }
    const int kt   = (row0 + rg * 8) / 64;
    const int tok0 = (row0 + rg * 8) % 64;
    *(uint4*)(&g_vt[kt * (HS * 64) + j * 64 + tok0]) = vt.u;
}

// ---------------------------------------------------------------------------
// Kernel 2: mma.sync fp16 split-K causal flash attention (m=0, P in registers)
// ---------------------------------------------------------------------------
__device__ __forceinline__ void issue_tile(uint32_t sb, int tid, int buf,
                                           int b, int ktile)
{
    const char* kp = (const char*)g_k + (size_t)(b * TSEQ + ktile * 64) * HS * 2;
    const char* vp = (const char*)g_vt + (size_t)(b * 64 + ktile) * (HS * 64) * 2;
#pragma unroll
    for (int rep = 0; rep < 2; rep++) {
        const int idx = tid + rep * 256;
        const int row = idx >> 3, c = idx & 7;
        const int dsw = row * 128 + ((c ^ (row & 7)) * 16);
        const int ssw = row * 128 + c * 16;
        cpa16(sb + OFF_K + buf * 8192 + dsw, kp + ssw);
        cpa16(sb + OFF_V + buf * 8192 + dsw, vp + ssw);
    }
}

__global__ __launch_bounds__(256, 2) void attn_kernel()
{
    extern __shared__ char sm[];
    const uint32_t sb = smem_u32(sm);
    const int tid  = threadIdx.x;
    const int w    = tid >> 5;
    const int lane = tid & 31;
    const int gid  = lane >> 2;
    const int tig  = lane & 3;
    const unsigned FULL = 0xffffffffu;

    // ---- decode blockIdx (heavy items first) ----
    const int b = blockIdx.x & 3;
    const int i = 143 - (int)(blockIdx.x >> 2);
    int g = 1;
    while (i >= 2 * g * (g + 1)) g++;
    const int off = i - 2 * g * (g - 1);
    const int qt = 4 * (g - 1) + off / g;
    const int ch = off % g;
    const int k0t = ch * 8;
    const int n = min(k0t + 8, 2 * qt + 2) - k0t;

    // ---- Q A-fragments ----
    uint32_t qf[4][4];
    {
        const __half* qb = g_q + (size_t)(b * TSEQ + qt * 128 + w * 16) * HS;
#pragma unroll
        for (int kk = 0; kk < 4; kk++) {
            const int cA = kk * 16 + tig * 2;
            qf[kk][0] = *(const uint32_t*)(qb + gid * HS + cA);
            qf[kk][1] = *(const uint32_t*)(qb + (gid + 8) * HS + cA);
            qf[kk][2] = *(const uint32_t*)(qb + gid * HS + cA + 8);
            qf[kk][3] = *(const uint32_t*)(qb + (gid + 8) * HS + cA + 8);
        }
    }

    float oacc[8][4];
#pragma unroll
    for (int j = 0; j < 8; j++)
#pragma unroll
        for (int q = 0; q < 4; q++) oacc[j][q] = 0.f;
    float lsumA = 0.f, lsumB = 0.f;
    const int growA = qt * 128 + w * 16 + gid;
    const int growB = growA + 8;
    const int wrow0 = qt * 128 + w * 16;    // smallest q row in this warp

    const int lgrp = lane >> 3, li = lane & 7;
    const int rsel = (lgrp >> 1) * 8 + li;
    const int csel = lgrp & 1;

    issue_tile(sb, tid, 0, b, k0t);
    cpa_commit();

    for (int t = 0; t < n; t++) {
        const int buf = t & 1;
        if (t + 1 < n) issue_tile(sb, tid, buf ^ 1, b, k0t + t + 1);
        cpa_commit();
        cpa_wait1();
        __syncthreads();

        const uint32_t kbase = sb + OFF_K + buf * 8192;
        const uint32_t vbase = sb + OFF_V + buf * 8192;

        // ---- S = Q K^T (ldsm hoisted per k-chunk) ----
        float sacc[8][4];
#pragma unroll
        for (int j = 0; j < 8; j++)
#pragma unroll
            for (int q = 0; q < 4; q++) sacc[j][q] = 0.f;

#pragma unroll
        for (int kk = 0; kk < 4; kk++) {
            const int c = kk * 2 + csel;
            uint32_t bh[4][4];
#pragma unroll
            for (int jp = 0; jp < 4; jp++) {
                const int tok = jp * 16 + rsel;
                ldsm4(bh[jp], kbase + tok * 128 + ((c ^ (tok & 7)) * 16));
            }
#pragma unroll
            for (int jp = 0; jp < 4; jp++) {
                mma16816(sacc[2 * jp],     qf[kk], bh[jp][0], bh[jp][1]);
                mma16816(sacc[2 * jp + 1], qf[kk], bh[jp][2], bh[jp][3]);
            }
        }

        // ---- epilogue: exp (+ mask only on diagonal warp-tiles) ----
        uint32_t pf[4][4];
        const bool full = ((k0t + t) * 64 + 63) <= wrow0;   // warp-uniform
        if (full) {
#pragma unroll
            for (int j = 0; j < 8; j++) {
                float p0 = ex2(sacc[j][0]);
                float p1 = ex2(sacc[j][1]);
                float p2 = ex2(sacc[j][2]);
                float p3 = ex2(sacc[j][3]);
                lsumA += p0 + p1;
                lsumB += p2 + p3;
                __half2 hA = __floats2half2_rn(p0, p1);
                __half2 hB = __floats2half2_rn(p2, p3);
                const int kt = j >> 1, hi = (j & 1) * 2;
                pf[kt][hi]     = *(uint32_t*)&hA;
                pf[kt][hi + 1] = *(uint32_t*)&hB;
            }
        } else {
#pragma unroll
            for (int j = 0; j < 8; j++) {
                const int tok0 = (k0t + t) * 64 + j * 8 + tig * 2;
                float p0 = (tok0     <= growA) ? ex2(sacc[j][0]) : 0.f;
                float p1 = (tok0 + 1 <= growA) ? ex2(sacc[j][1]) : 0.f;
                float p2 = (tok0     <= growB) ? ex2(sacc[j][2]) : 0.f;
                float p3 = (tok0 + 1 <= growB) ? ex2(sacc[j][3]) : 0.f;
                lsumA += p0 + p1;
                lsumB += p2 + p3;
                __half2 hA = __floats2half2_rn(p0, p1);
                __half2 hB = __floats2half2_rn(p2, p3);
                const int kt = j >> 1, hi = (j & 1) * 2;
                pf[kt][hi]     = *(uint32_t*)&hA;
                pf[kt][hi + 1] = *(uint32_t*)&hB;
            }
        }

        // ---- O += P V (ldsm hoisted per token-chunk) ----
#pragma unroll
        for (int kt = 0; kt < 4; kt++) {
            const int c = kt * 2 + csel;
            uint32_t vh[4][4];
#pragma unroll
            for (int jdp = 0; jdp < 4; jdp++) {
                const int dim = jdp * 16 + rsel;
                ldsm4(vh[jdp], vbase + dim * 128 + ((c ^ (dim & 7)) * 16));
            }
#pragma unroll
            for (int jdp = 0; jdp < 4; jdp++) {
                mma16816(oacc[2 * jdp],     pf[kt], vh[jdp][0], vh[jdp][1]);
                mma16816(oacc[2 * jdp + 1], pf[kt], vh[jdp][2], vh[jdp][3]);
            }
        }
        __syncthreads();
    }

    // ---- reduce row sums across the 4-lane quad ----
    lsumA += __shfl_xor_sync(FULL, lsumA, 1);
    lsumA += __shfl_xor_sync(FULL, lsumA, 2);
    lsumB += __shfl_xor_sync(FULL, lsumB, 1);
    lsumB += __shfl_xor_sync(FULL, lsumB, 2);

    // ---- store partials ----
    const size_t pbase = (((size_t)(b * NQT + qt) * MAXCH + ch) * 128) * HS;
    const int rowA = w * 16 + gid;
#pragma unroll
    for (int jd = 0; jd < 8; jd++) {
        const int col = jd * 8 + tig * 2;
        *(float2*)(&g_part[pbase + (size_t)rowA * HS + col]) =
            make_float2(oacc[jd][0], oacc[jd][1]);
        *(float2*)(&g_part[pbase + (size_t)(rowA + 8) * HS + col]) =
            make_float2(oacc[jd][2], oacc[jd][3]);
    }
    if (tig == 0) {
        const size_t lbase = (((size_t)(b * NQT + qt) * MAXCH + ch) * 128);
        g_l[lbase + rowA] = lsumA;
        g_l[lbase + rowA + 8] = lsumB;
    }
}

// ---------------------------------------------------------------------------
// Kernel 3: merge split-K partials. Grid 1024 = (b, qt, 8 row-groups);
// thread = one float4 of one row -> short latency chains, full chip.
// ---------------------------------------------------------------------------
__global__ __launch_bounds__(256) void merge_kernel(float* __restrict__ out)
{
    const int bid = blockIdx.x;
    const int rg  = bid & 7;
    const int qt  = (bid >> 3) & 31;
    const int b   = bid >> 8;
    const int nch = qt / 4 + 1;
    const int tid = threadIdx.x;
    const int row = rg * 16 + (tid >> 4);   // 0..127
    const int d0  = (tid & 15) * 4;

    const size_t base = (size_t)(b * NQT + qt) * MAXCH * 128;
    float4 acc = make_float4(0.f, 0.f, 0.f, 0.f);
    float L = 0.f;
#pragma unroll 4
    for (int c = 0; c < nch; c++) {
        L += g_l[base + c * 128 + row];
        const float4 v = *(const float4*)(&g_part[(base + c * 128 + row) * HS + d0]);
        acc.x += v.x; acc.y += v.y; acc.z += v.z; acc.w += v.w;
    }
    const float inv = 1.f / L;
    float* op = out + ((size_t)b * TSEQ + qt * 128 + row) * HS + d0;
    *(float4*)op = make_float4(acc.x * inv, acc.y * inv, acc.z * inv, acc.w * inv);
}

// ---------------------------------------------------------------------------
extern "C" void kernel_launch(void* const* d_in, const int* in_sizes, int n_in,
                              void* d_out, int out_size)
{
    const float* x  = (const float*)d_in[0];
    const float* Wq = (const float*)d_in[1];
    const float* Wk = (const float*)d_in[2];
    const float* Wv = (const float*)d_in[3];
    float* out = (float*)d_out;

    cudaFuncSetAttribute(attn_kernel, cudaFuncAttributeMaxDynamicSharedMemorySize, SMEM_TOTAL);

    wt_kernel<<<25, 256>>>(Wq, Wk, Wv);
    proj_kernel<<<512, 256>>>(x);
    attn_kernel<<<BATCH * ITEMS_PER_B, 256, SMEM_TOTAL>>>();
    merge_kernel<<<BATCH * NQT * 8, 256>>>(out);
}

// round 8
// speedup vs baseline: 14.1040x; 1.0359x over previous
#include <cuda_runtime.h>
#include <cuda_fp16.h>
#include <cstdint>
#include <math.h>

#define BATCH 4
#define TSEQ  4096
#define EMB   100
#define HS    64
#define NQT   32            // 128-row q tiles per batch
#define MAXCH 8
#define ITEMS_PER_B 144     // sum over qt of ceil((qt+1)/4)

// ---------------- global scratch ----------------
__device__ __align__(16) __half g_q[BATCH * TSEQ * HS];          // q * log2e/8, fp16
__device__ __align__(16) __half g_k[BATCH * TSEQ * HS];          // fp16
__device__ __align__(16) __half g_vt[BATCH * 64 * HS * 64];      // [ktile][dim][tok]
__device__ __align__(16) float g_wt[3 * HS * EMB];               // W^T: [mat][j][e]
__device__ float g_part[BATCH * NQT * MAXCH * 128 * HS];         // unnormalized O
__device__ float g_l[BATCH * NQT * MAXCH * 128];                 // row sums

// ---------------- PTX helpers (arch-portable, sm_80-era) ---------------
__device__ __forceinline__ uint32_t smem_u32(const void* p) {
    uint32_t a;
    asm("{ .reg .u64 t; cvta.to.shared.u64 t, %1; cvt.u32.u64 %0, t; }" : "=r"(a) : "l"(p));
    return a;
}
__device__ __forceinline__ uint32_t h2ex2(uint32_t x) {
    uint32_t r; asm("ex2.approx.f16x2 %0, %1;" : "=r"(r) : "r"(x)); return r;
}
__device__ __forceinline__ void cpa16(uint32_t dst, const void* src) {
    asm volatile("cp.async.cg.shared.global [%0], [%1], 16;" :: "r"(dst), "l"(src));
}
__device__ __forceinline__ void cpa_commit() { asm volatile("cp.async.commit_group;" ::: "memory"); }
__device__ __forceinline__ void cpa_wait1()  { asm volatile("cp.async.wait_group 1;" ::: "memory"); }
__device__ __forceinline__ void ldsm4(uint32_t* r, uint32_t addr) {
    asm volatile("ldmatrix.sync.aligned.m8n8.x4.shared.b16 {%0,%1,%2,%3}, [%4];"
        : "=r"(r[0]), "=r"(r[1]), "=r"(r[2]), "=r"(r[3]) : "r"(addr));
}
__device__ __forceinline__ void mma16816(float* c, const uint32_t* a, uint32_t b0, uint32_t b1) {
    asm volatile("mma.sync.aligned.m16n8k16.row.col.f32.f16.f16.f32 "
        "{%0,%1,%2,%3}, {%4,%5,%6,%7}, {%8,%9}, {%0,%1,%2,%3};"
        : "+f"(c[0]), "+f"(c[1]), "+f"(c[2]), "+f"(c[3])
        : "r"(a[0]), "r"(a[1]), "r"(a[2]), "r"(a[3]), "r"(b0), "r"(b1));
}

// SMEM: K and V tile PAIRS, double buffered (16KB per pair per part)
#define OFF_K 0
#define OFF_V 32768
#define SMEM_TOTAL 65536

// ---------------------------------------------------------------------------
// Kernel 0: transpose W -> g_wt[mat][j][e]
// ---------------------------------------------------------------------------
__global__ void wt_kernel(const float* __restrict__ Wq,
                          const float* __restrict__ Wk,
                          const float* __restrict__ Wv)
{
    for (int i = blockIdx.x * 256 + threadIdx.x; i < HS * EMB; i += gridDim.x * 256) {
        const int j = i / EMB, e = i % EMB;
        g_wt[0 * HS * EMB + i] = Wq[e * HS + j];
        g_wt[1 * HS * EMB + i] = Wk[e * HS + j];
        g_wt[2 * HS * EMB + i] = Wv[e * HS + j];
    }
}

// ---------------------------------------------------------------------------
// Kernel 1: fused Q/K/V projection -> fp16 (V transposed per 64-token tile)
// ---------------------------------------------------------------------------
__global__ __launch_bounds__(256) void proj_kernel(const float* __restrict__ x)
{
    __shared__ float xs[32][EMB];
    const int tid = threadIdx.x;
    const int row0 = blockIdx.x * 32;

    for (int i = tid; i < 32 * EMB; i += 256)
        xs[i / EMB][i % EMB] = x[row0 * EMB + i];
    __syncthreads();

    const int j  = tid & 63;
    const int rg = tid >> 6;

    float q[8], k[8], v[8];
#pragma unroll
    for (int rr = 0; rr < 8; rr++) { q[rr] = 0.f; k[rr] = 0.f; v[rr] = 0.f; }

    const float4* wq4 = (const float4*)(g_wt + 0 * HS * EMB + j * EMB);
    const float4* wk4 = (const float4*)(g_wt + 1 * HS * EMB + j * EMB);
    const float4* wv4 = (const float4*)(g_wt + 2 * HS * EMB + j * EMB);

#pragma unroll
    for (int e4 = 0; e4 < EMB / 4; e4++) {
        const float4 wq = wq4[e4];
        const float4 wk = wk4[e4];
        const float4 wv = wv4[e4];
#pragma unroll
        for (int rr = 0; rr < 8; rr++) {
            const float4 xv = *(const float4*)(&xs[rg * 8 + rr][e4 * 4]);
            q[rr] = fmaf(xv.x, wq.x, q[rr]); q[rr] = fmaf(xv.y, wq.y, q[rr]);
            q[rr] = fmaf(xv.z, wq.z, q[rr]); q[rr] = fmaf(xv.w, wq.w, q[rr]);
            k[rr] = fmaf(xv.x, wk.x, k[rr]); k[rr] = fmaf(xv.y, wk.y, k[rr]);
            k[rr] = fmaf(xv.z, wk.z, k[rr]); k[rr] = fmaf(xv.w, wk.w, k[rr]);
            v[rr] = fmaf(xv.x, wv.x, v[rr]); v[rr] = fmaf(xv.y, wv.y, v[rr]);
            v[rr] = fmaf(xv.z, wv.z, v[rr]); v[rr] = fmaf(xv.w, wv.w, v[rr]);
        }
    }

    const float QSCALE = 0.125f * 1.4426950408889634f;   // fold 1/8 * log2(e)
    union { __half h[8]; uint4 u; } vt;
#pragma unroll
    for (int rr = 0; rr < 8; rr++) {
        const int row = row0 + rg * 8 + rr;
        g_q[row * HS + j] = __float2half_rn(q[rr] * QSCALE);
        g_k[row * HS + j] = __float2half_rn(k[rr]);
        vt.h[rr] = __float2half_rn(v[rr]);
    }
    const int kt   = (row0 + rg * 8) / 64;
    const int tok0 = (row0 + rg * 8) % 64;
    *(uint4*)(&g_vt[kt * (HS * 64) + j * 64 + tok0]) = vt.u;
}

// ---------------------------------------------------------------------------
// Kernel 2: mma.sync fp16 split-K causal flash attention.
// Pairs of 64-token k-tiles per pipeline step; half2 exp epilogue.
// ---------------------------------------------------------------------------
__device__ __forceinline__ void issue_pair(uint32_t sb, int tid, int buf,
                                           int b, int ktile)
{
    const char* kp = (const char*)g_k + (size_t)(b * TSEQ + ktile * 64) * HS * 2;
    const char* vp = (const char*)g_vt + (size_t)(b * 64 + ktile) * (HS * 64) * 2;
#pragma unroll
    for (int rep = 0; rep < 4; rep++) {             // 1024 chunks over both tiles
        const int idx = tid + rep * 256;            // 16B chunk index 0..1023
        const int row = idx >> 3, c = idx & 7;      // row 0..127 spans both tiles
        const int dsw = row * 128 + ((c ^ (row & 7)) * 16);
        const int ssw = row * 128 + c * 16;
        cpa16(sb + OFF_K + buf * 16384 + dsw, kp + ssw);
        cpa16(sb + OFF_V + buf * 16384 + dsw, vp + ssw);
    }
}

__global__ __launch_bounds__(256, 2) void attn_kernel()
{
    extern __shared__ char sm[];
    const uint32_t sb = smem_u32(sm);
    const int tid  = threadIdx.x;
    const int w    = tid >> 5;
    const int lane = tid & 31;
    const int gid  = lane >> 2;
    const int tig  = lane & 3;
    const unsigned FULL = 0xffffffffu;

    // ---- decode blockIdx (heavy items first) ----
    const int b = blockIdx.x & 3;
    const int i = 143 - (int)(blockIdx.x >> 2);
    int g = 1;
    while (i >= 2 * g * (g + 1)) g++;
    const int off = i - 2 * g * (g - 1);
    const int qt = 4 * (g - 1) + off / g;
    const int ch = off % g;
    const int k0t = ch * 8;
    const int n = min(k0t + 8, 2 * qt + 2) - k0t;   // even, >=2
    const int np = n >> 1;                          // pairs

    // ---- Q A-fragments ----
    uint32_t qf[4][4];
    {
        const __half* qb = g_q + (size_t)(b * TSEQ + qt * 128 + w * 16) * HS;
#pragma unroll
        for (int kk = 0; kk < 4; kk++) {
            const int cA = kk * 16 + tig * 2;
            qf[kk][0] = *(const uint32_t*)(qb + gid * HS + cA);
            qf[kk][1] = *(const uint32_t*)(qb + (gid + 8) * HS + cA);
            qf[kk][2] = *(const uint32_t*)(qb + gid * HS + cA + 8);
            qf[kk][3] = *(const uint32_t*)(qb + (gid + 8) * HS + cA + 8);
        }
    }

    float oacc[8][4];
#pragma unroll
    for (int j = 0; j < 8; j++)
#pragma unroll
        for (int q = 0; q < 4; q++) oacc[j][q] = 0.f;
    float lsumA = 0.f, lsumB = 0.f;
    const int growA = qt * 128 + w * 16 + gid;
    const int growB = growA + 8;
    const int wrow0 = qt * 128 + w * 16;

    const int lgrp = lane >> 3, li = lane & 7;
    const int rsel = (lgrp >> 1) * 8 + li;
    const int csel = lgrp & 1;

    issue_pair(sb, tid, 0, b, k0t);
    cpa_commit();

    for (int pt = 0; pt < np; pt++) {
        const int buf = pt & 1;
        if (pt + 1 < np) issue_pair(sb, tid, buf ^ 1, b, k0t + 2 * (pt + 1));
        cpa_commit();
        cpa_wait1();
        __syncthreads();

#pragma unroll
        for (int sub = 0; sub < 2; sub++) {
            const int tglob = k0t + 2 * pt + sub;           // 64-token tile index
            const uint32_t kbase = sb + OFF_K + buf * 16384 + sub * 8192;
            const uint32_t vbase = sb + OFF_V + buf * 16384 + sub * 8192;

            // ---- S = Q K^T ----
            float sacc[8][4];
#pragma unroll
            for (int j = 0; j < 8; j++)
#pragma unroll
                for (int q = 0; q < 4; q++) sacc[j][q] = 0.f;

#pragma unroll
            for (int kk = 0; kk < 4; kk++) {
                const int c = kk * 2 + csel;
                uint32_t bh[4][4];
#pragma unroll
                for (int jp = 0; jp < 4; jp++) {
                    const int tok = jp * 16 + rsel;
                    ldsm4(bh[jp], kbase + tok * 128 + ((c ^ (tok & 7)) * 16));
                }
#pragma unroll
                for (int jp = 0; jp < 4; jp++) {
                    mma16816(sacc[2 * jp],     qf[kk], bh[jp][0], bh[jp][1]);
                    mma16816(sacc[2 * jp + 1], qf[kk], bh[jp][2], bh[jp][3]);
                }
            }

            // ---- epilogue: half2 exp (+AND-mask on diagonal warp-tiles) ----
            uint32_t pf[4][4];
            __half2 lA2 = __floats2half2_rn(0.f, 0.f);
            __half2 lB2 = lA2;
            const bool full = (tglob * 64 + 63) <= wrow0;   // warp-uniform
            if (full) {
#pragma unroll
                for (int j = 0; j < 8; j++) {
                    __half2 hA = __floats2half2_rn(sacc[j][0], sacc[j][1]);
                    __half2 hB = __floats2half2_rn(sacc[j][2], sacc[j][3]);
                    uint32_t pa = h2ex2(*(uint32_t*)&hA);
                    uint32_t pb = h2ex2(*(uint32_t*)&hB);
                    lA2 = __hadd2(lA2, *(__half2*)&pa);
                    lB2 = __hadd2(lB2, *(__half2*)&pb);
                    const int kt = j >> 1, hi = (j & 1) * 2;
                    pf[kt][hi]     = pa;
                    pf[kt][hi + 1] = pb;
                }
            } else {
#pragma unroll
                for (int j = 0; j < 8; j++) {
                    const int tok0 = tglob * 64 + j * 8 + tig * 2;
                    const uint32_t mA = (tok0 + 1 <= growA) ? 0xFFFFFFFFu
                                       : ((tok0 <= growA) ? 0x0000FFFFu : 0u);
                    const uint32_t mB = (tok0 + 1 <= growB) ? 0xFFFFFFFFu
                                       : ((tok0 <= growB) ? 0x0000FFFFu : 0u);
                    __half2 hA = __floats2half2_rn(sacc[j][0], sacc[j][1]);
                    __half2 hB = __floats2half2_rn(sacc[j][2], sacc[j][3]);
                    uint32_t pa = h2ex2(*(uint32_t*)&hA) & mA;
                    uint32_t pb = h2ex2(*(uint32_t*)&hB) & mB;
                    lA2 = __hadd2(lA2, *(__half2*)&pa);
                    lB2 = __hadd2(lB2, *(__half2*)&pb);
                    const int kt = j >> 1, hi = (j & 1) * 2;
                    pf[kt][hi]     = pa;
                    pf[kt][hi + 1] = pb;
                }
            }
            {   // fold per-tile half2 sums into fp32 accumulators
                float2 fA = __half22float2(lA2);
                float2 fB = __half22float2(lB2);
                lsumA += fA.x + fA.y;
                lsumB += fB.x + fB.y;
            }

            // ---- O += P V ----
#pragma unroll
            for (int kt = 0; kt < 4; kt++) {
                const int c = kt * 2 + csel;
                uint32_t vh[4][4];
#pragma unroll
                for (int jdp = 0; jdp < 4; jdp++) {
                    const int dim = jdp * 16 + rsel;
                    ldsm4(vh[jdp], vbase + dim * 128 + ((c ^ (dim & 7)) * 16));
                }
#pragma unroll
                for (int jdp = 0; jdp < 4; jdp++) {
                    mma16816(oacc[2 * jdp],     pf[kt], vh[jdp][0], vh[jdp][1]);
                    mma16816(oacc[2 * jdp + 1], pf[kt], vh[jdp][2], vh[jdp][3]);
                }
            }
        }
        __syncthreads();
    }

    // ---- reduce row sums across the 4-lane quad ----
    lsumA += __shfl_xor_sync(FULL, lsumA, 1);
    lsumA += __shfl_xor_sync(FULL, lsumA, 2);
    lsumB += __shfl_xor_sync(FULL, lsumB, 1);
    lsumB += __shfl_xor_sync(FULL, lsumB, 2);

    // ---- store partials ----
    const size_t pbase = (((size_t)(b * NQT + qt) * MAXCH + ch) * 128) * HS;
    const int rowA = w * 16 + gid;
#pragma unroll
    for (int jd = 0; jd < 8; jd++) {
        const int col = jd * 8 + tig * 2;
        *(float2*)(&g_part[pbase + (size_t)rowA * HS + col]) =
            make_float2(oacc[jd][0], oacc[jd][1]);
        *(float2*)(&g_part[pbase + (size_t)(rowA + 8) * HS + col]) =
            make_float2(oacc[jd][2], oacc[jd][3]);
    }
    if (tig == 0) {
        const size_t lbase = (((size_t)(b * NQT + qt) * MAXCH + ch) * 128);
        g_l[lbase + rowA] = lsumA;
        g_l[lbase + rowA + 8] = lsumB;
    }
}

// ---------------------------------------------------------------------------
// Kernel 3: merge split-K partials (grid 1024, near LTS cap — unchanged)
// ---------------------------------------------------------------------------
__global__ __launch_bounds__(256) void merge_kernel(float* __restrict__ out)
{
    const int bid = blockIdx.x;
    const int rg  = bid & 7;
    const int qt  = (bid >> 3) & 31;
    const int b   = bid >> 8;
    const int nch = qt / 4 + 1;
    const int tid = threadIdx.x;
    const int row = rg * 16 + (tid >> 4);
    const int d0  = (tid & 15) * 4;

    const size_t base = (size_t)(b * NQT + qt) * MAXCH * 128;
    float4 acc = make_float4(0.f, 0.f, 0.f, 0.f);
    float L = 0.f;
#pragma unroll 4
    for (int c = 0; c < nch; c++) {
        L += g_l[base + c * 128 + row];
        const float4 v = *(const float4*)(&g_part[(base + c * 128 + row) * HS + d0]);
        acc.x += v.x; acc.y += v.y; acc.z += v.z; acc.w += v.w;
    }
    const float inv = 1.f / L;
    float* op = out + ((size_t)b * TSEQ + qt * 128 + row) * HS + d0;
    *(float4*)op = make_float4(acc.x * inv, acc.y * inv, acc.z * inv, acc.w * inv);
}

// ---------------------------------------------------------------------------
extern "C" void kernel_launch(void* const* d_in, const int* in_sizes, int n_in,
                              void* d_out, int out_size)
{
    const float* x  = (const float*)d_in[0];
    const float* Wq = (const float*)d_in[1];
    const float* Wk = (const float*)d_in[2];
    const float* Wv = (const float*)d_in[3];
    float* out = (float*)d_out;

    cudaFuncSetAttribute(attn_kernel, cudaFuncAttributeMaxDynamicSharedMemorySize, SMEM_TOTAL);

    wt_kernel<<<25, 256>>>(Wq, Wk, Wv);
    proj_kernel<<<512, 256>>>(x);
    attn_kernel<<<BATCH * ITEMS_PER_B, 256, SMEM_TOTAL>>>();
    merge_kernel<<<BATCH * NQT * 8, 256>>>(out);
}

// round 9
// speedup vs baseline: 15.7664x; 1.1179x over previous
#include <cuda_runtime.h>
#include <cuda_fp16.h>
#include <cstdint>
#include <math.h>

#define BATCH 4
#define TSEQ  4096
#define EMB   100
#define HS    64
#define NQT   32            // 128-row q tiles per batch
#define MAXCH 8
#define ITEMS_PER_B 144     // sum over qt of ceil((qt+1)/4)

// ---------------- global scratch ----------------
__device__ __align__(16) __half g_q[BATCH * TSEQ * HS];          // q * log2e/8, fp16
__device__ __align__(16) __half g_k[BATCH * TSEQ * HS];          // fp16
__device__ __align__(16) __half g_vt[BATCH * 64 * HS * 64];      // [ktile][dim][tok]
__device__ __align__(16) float g_wp[3 * 50 * HS * 2];            // W pairs: [m][e/2][j][2]
__device__ float g_part[BATCH * NQT * MAXCH * 128 * HS];         // unnormalized O
__device__ float g_l[BATCH * NQT * MAXCH * 128];                 // row sums

// ---------------- PTX helpers ---------------
__device__ __forceinline__ uint32_t smem_u32(const void* p) {
    uint32_t a;
    asm("{ .reg .u64 t; cvta.to.shared.u64 t, %1; cvt.u32.u64 %0, t; }" : "=r"(a) : "l"(p));
    return a;
}
__device__ __forceinline__ uint32_t h2ex2(uint32_t x) {
    uint32_t r; asm("ex2.approx.f16x2 %0, %1;" : "=r"(r) : "r"(x)); return r;
}
__device__ __forceinline__ void ffma2(unsigned long long& d,
                                      unsigned long long a, unsigned long long b) {
    asm("fma.rn.f32x2 %0, %1, %2, %0;" : "+l"(d) : "l"(a), "l"(b));
}
__device__ __forceinline__ void cpa16(uint32_t dst, const void* src) {
    asm volatile("cp.async.cg.shared.global [%0], [%1], 16;" :: "r"(dst), "l"(src));
}
__device__ __forceinline__ void cpa_commit() { asm volatile("cp.async.commit_group;" ::: "memory"); }
__device__ __forceinline__ void cpa_wait1()  { asm volatile("cp.async.wait_group 1;" ::: "memory"); }
__device__ __forceinline__ void ldsm4(uint32_t* r, uint32_t addr) {
    asm volatile("ldmatrix.sync.aligned.m8n8.x4.shared.b16 {%0,%1,%2,%3}, [%4];"
        : "=r"(r[0]), "=r"(r[1]), "=r"(r[2]), "=r"(r[3]) : "r"(addr));
}
__device__ __forceinline__ void mma16816(float* c, const uint32_t* a, uint32_t b0, uint32_t b1) {
    asm volatile("mma.sync.aligned.m16n8k16.row.col.f32.f16.f16.f32 "
        "{%0,%1,%2,%3}, {%4,%5,%6,%7}, {%8,%9}, {%0,%1,%2,%3};"
        : "+f"(c[0]), "+f"(c[1]), "+f"(c[2]), "+f"(c[3])
        : "r"(a[0]), "r"(a[1]), "r"(a[2]), "r"(a[3]), "r"(b0), "r"(b1));
}

// attn SMEM: K and V tile PAIRS, double buffered
#define OFF_K 0
#define OFF_V 32768
#define SMEM_TOTAL 65536

// proj SMEM
#define XS_PAD 102
#define PROJ_XS_FLOATS (128 * XS_PAD)
#define PROJ_WS_FLOATS (3 * 50 * HS * 2)
#define PROJ_SMEM ((PROJ_XS_FLOATS + PROJ_WS_FLOATS) * 4)

// ---------------------------------------------------------------------------
// Kernel 0: repack W -> g_wp[m][e/2][j][2]  (e-pair interleaved for f32x2)
// ---------------------------------------------------------------------------
__global__ void wp_kernel(const float* __restrict__ Wq,
                          const float* __restrict__ Wk,
                          const float* __restrict__ Wv)
{
    for (int i = blockIdx.x * 256 + threadIdx.x; i < 3 * 50 * HS; i += gridDim.x * 256) {
        const int m = i / (50 * HS);
        const int r = i % (50 * HS);
        const int ep = r / HS, j = r % HS;
        const float* W = (m == 0) ? Wq : ((m == 1) ? Wk : Wv);
        g_wp[i * 2 + 0] = W[(2 * ep)     * HS + j];
        g_wp[i * 2 + 1] = W[(2 * ep + 1) * HS + j];
    }
}

// ---------------------------------------------------------------------------
// Kernel 1: fused Q/K/V projection, SMEM-tiled, packed f32x2 FMA.
// Grid 128: CTA = 128 rows x 192 cols. Thread = 8 rows x 4 j, m-loop over
// the 3 matrices reusing 32 f32x2 accumulators.
// ---------------------------------------------------------------------------
__global__ __launch_bounds__(256) void proj_kernel(const float* __restrict__ x)
{
    extern __shared__ float psm[];
    float* xs = psm;                        // [128][XS_PAD]
    float* ws = psm + PROJ_XS_FLOATS;       // [3][50][64][2]

    const int tid = threadIdx.x;
    const int row0g = blockIdx.x * 128;

    // cooperative loads (coalesced)
    const float* xg = x + (size_t)row0g * EMB;
    for (int i = tid; i < 128 * EMB; i += 256)
        xs[(i / EMB) * XS_PAD + (i % EMB)] = xg[i];
    for (int i = tid; i < PROJ_WS_FLOATS / 4; i += 256)
        *(float4*)(ws + i * 4) = *(const float4*)(g_wp + i * 4);
    __syncthreads();

    const int rt = tid >> 4;        // 0..15 -> 8 rows each
    const int ct = tid & 15;        // 0..15 -> 4 j each
    const int row0 = rt * 8;
    const int j0 = ct * 4;

    const float QSCALE = 0.125f * 1.4426950408889634f;   // 1/8 * log2(e)

#pragma unroll 1
    for (int m = 0; m < 3; m++) {
        unsigned long long acc[32];
#pragma unroll
        for (int q = 0; q < 32; q++) acc[q] = 0ull;

        const float* wsm = ws + m * (50 * HS * 2) + j0 * 2;
#pragma unroll 2
        for (int ep = 0; ep < 50; ep++) {
            unsigned long long xv[8];
#pragma unroll
            for (int r = 0; r < 8; r++)
                xv[r] = *(const unsigned long long*)(&xs[(row0 + r) * XS_PAD + 2 * ep]);
            const ulonglong2 wa = *(const ulonglong2*)(wsm + ep * (HS * 2));     // j0, j0+1
            const ulonglong2 wb = *(const ulonglong2*)(wsm + ep * (HS * 2) + 4); // j0+2, j0+3
#pragma unroll
            for (int r = 0; r < 8; r++) {
                ffma2(acc[r * 4 + 0], xv[r], wa.x);
                ffma2(acc[r * 4 + 1], xv[r], wa.y);
                ffma2(acc[r * 4 + 2], xv[r], wb.x);
                ffma2(acc[r * 4 + 3], xv[r], wb.y);
            }
        }

        // fold partial-sum pairs
        float val[32];
#pragma unroll
        for (int q = 0; q < 32; q++) {
            const float2 f = *(float2*)&acc[q];
            val[q] = f.x + f.y;
        }

        if (m == 0) {          // Q: scale and store [row][j]
#pragma unroll
            for (int r = 0; r < 8; r++) {
                __half2 h01 = __floats2half2_rn(val[r*4+0] * QSCALE, val[r*4+1] * QSCALE);
                __half2 h23 = __floats2half2_rn(val[r*4+2] * QSCALE, val[r*4+3] * QSCALE);
                uint2 u = make_uint2(*(uint32_t*)&h01, *(uint32_t*)&h23);
                *(uint2*)(&g_q[(size_t)(row0g + row0 + r) * HS + j0]) = u;
            }
        } else if (m == 1) {   // K: store [row][j]
#pragma unroll
            for (int r = 0; r < 8; r++) {
                __half2 h01 = __floats2half2_rn(val[r*4+0], val[r*4+1]);
                __half2 h23 = __floats2half2_rn(val[r*4+2], val[r*4+3]);
                uint2 u = make_uint2(*(uint32_t*)&h01, *(uint32_t*)&h23);
                *(uint2*)(&g_k[(size_t)(row0g + row0 + r) * HS + j0]) = u;
            }
        } else {               // V: transposed store [ktile][dim][tok]
            const int grow0 = row0g + row0;
            const int kt = grow0 >> 6;            // 8-row group never straddles 64
            const int tok0 = grow0 & 63;
#pragma unroll
            for (int jj = 0; jj < 4; jj++) {
                union { __half h[8]; uint4 u; } vt;
#pragma unroll
                for (int r = 0; r < 8; r++)
                    vt.h[r] = __float2half_rn(val[r * 4 + jj]);
                *(uint4*)(&g_vt[(size_t)kt * (HS * 64) + (j0 + jj) * 64 + tok0]) = vt.u;
            }
        }
    }
}

// ---------------------------------------------------------------------------
// Kernel 2: mma.sync fp16 split-K causal flash attention (unchanged from R8)
// ---------------------------------------------------------------------------
__device__ __forceinline__ void issue_pair(uint32_t sb, int tid, int buf,
                                           int b, int ktile)
{
    const char* kp = (const char*)g_k + (size_t)(b * TSEQ + ktile * 64) * HS * 2;
    const char* vp = (const char*)g_vt + (size_t)(b * 64 + ktile) * (HS * 64) * 2;
#pragma unroll
    for (int rep = 0; rep < 4; rep++) {
        const int idx = tid + rep * 256;
        const int row = idx >> 3, c = idx & 7;
        const int dsw = row * 128 + ((c ^ (row & 7)) * 16);
        const int ssw = row * 128 + c * 16;
        cpa16(sb + OFF_K + buf * 16384 + dsw, kp + ssw);
        cpa16(sb + OFF_V + buf * 16384 + dsw, vp + ssw);
    }
}

__global__ __launch_bounds__(256, 2) void attn_kernel()
{
    extern __shared__ char sm[];
    const uint32_t sb = smem_u32(sm);
    const int tid  = threadIdx.x;
    const int w    = tid >> 5;
    const int lane = tid & 31;
    const int gid  = lane >> 2;
    const int tig  = lane & 3;
    const unsigned FULL = 0xffffffffu;

    const int b = blockIdx.x & 3;
    const int i = 143 - (int)(blockIdx.x >> 2);
    int g = 1;
    while (i >= 2 * g * (g + 1)) g++;
    const int off = i - 2 * g * (g - 1);
    const int qt = 4 * (g - 1) + off / g;
    const int ch = off % g;
    const int k0t = ch * 8;
    const int n = min(k0t + 8, 2 * qt + 2) - k0t;
    const int np = n >> 1;

    uint32_t qf[4][4];
    {
        const __half* qb = g_q + (size_t)(b * TSEQ + qt * 128 + w * 16) * HS;
#pragma unroll
        for (int kk = 0; kk < 4; kk++) {
            const int cA = kk * 16 + tig * 2;
            qf[kk][0] = *(const uint32_t*)(qb + gid * HS + cA);
            qf[kk][1] = *(const uint32_t*)(qb + (gid + 8) * HS + cA);
            qf[kk][2] = *(const uint32_t*)(qb + gid * HS + cA + 8);
            qf[kk][3] = *(const uint32_t*)(qb + (gid + 8) * HS + cA + 8);
        }
    }

    float oacc[8][4];
#pragma unroll
    for (int j = 0; j < 8; j++)
#pragma unroll
        for (int q = 0; q < 4; q++) oacc[j][q] = 0.f;
    float lsumA = 0.f, lsumB = 0.f;
    const int growA = qt * 128 + w * 16 + gid;
    const int growB = growA + 8;
    const int wrow0 = qt * 128 + w * 16;

    const int lgrp = lane >> 3, li = lane & 7;
    const int rsel = (lgrp >> 1) * 8 + li;
    const int csel = lgrp & 1;

    issue_pair(sb, tid, 0, b, k0t);
    cpa_commit();

    for (int pt = 0; pt < np; pt++) {
        const int buf = pt & 1;
        if (pt + 1 < np) issue_pair(sb, tid, buf ^ 1, b, k0t + 2 * (pt + 1));
        cpa_commit();
        cpa_wait1();
        __syncthreads();

#pragma unroll
        for (int sub = 0; sub < 2; sub++) {
            const int tglob = k0t + 2 * pt + sub;
            const uint32_t kbase = sb + OFF_K + buf * 16384 + sub * 8192;
            const uint32_t vbase = sb + OFF_V + buf * 16384 + sub * 8192;

            float sacc[8][4];
#pragma unroll
            for (int j = 0; j < 8; j++)
#pragma unroll
                for (int q = 0; q < 4; q++) sacc[j][q] = 0.f;

#pragma unroll
            for (int kk = 0; kk < 4; kk++) {
                const int c = kk * 2 + csel;
                uint32_t bh[4][4];
#pragma unroll
                for (int jp = 0; jp < 4; jp++) {
                    const int tok = jp * 16 + rsel;
                    ldsm4(bh[jp], kbase + tok * 128 + ((c ^ (tok & 7)) * 16));
                }
#pragma unroll
                for (int jp = 0; jp < 4; jp++) {
                    mma16816(sacc[2 * jp],     qf[kk], bh[jp][0], bh[jp][1]);
                    mma16816(sacc[2 * jp + 1], qf[kk], bh[jp][2], bh[jp][3]);
                }
            }

            uint32_t pf[4][4];
            __half2 lA2 = __floats2half2_rn(0.f, 0.f);
            __half2 lB2 = lA2;
            const bool full = (tglob * 64 + 63) <= wrow0;
            if (full) {
#pragma unroll
                for (int j = 0; j < 8; j++) {
                    __half2 hA = __floats2half2_rn(sacc[j][0], sacc[j][1]);
                    __half2 hB = __floats2half2_rn(sacc[j][2], sacc[j][3]);
                    uint32_t pa = h2ex2(*(uint32_t*)&hA);
                    uint32_t pb = h2ex2(*(uint32_t*)&hB);
                    lA2 = __hadd2(lA2, *(__half2*)&pa);
                    lB2 = __hadd2(lB2, *(__half2*)&pb);
                    const int kt = j >> 1, hi = (j & 1) * 2;
                    pf[kt][hi]     = pa;
                    pf[kt][hi + 1] = pb;
                }
            } else {
#pragma unroll
                for (int j = 0; j < 8; j++) {
                    const int tok0 = tglob * 64 + j * 8 + tig * 2;
                    const uint32_t mA = (tok0 + 1 <= growA) ? 0xFFFFFFFFu
                                       : ((tok0 <= growA) ? 0x0000FFFFu : 0u);
                    const uint32_t mB = (tok0 + 1 <= growB) ? 0xFFFFFFFFu
                                       : ((tok0 <= growB) ? 0x0000FFFFu : 0u);
                    __half2 hA = __floats2half2_rn(sacc[j][0], sacc[j][1]);
                    __half2 hB = __floats2half2_rn(sacc[j][2], sacc[j][3]);
                    uint32_t pa = h2ex2(*(uint32_t*)&hA) & mA;
                    uint32_t pb = h2ex2(*(uint32_t*)&hB) & mB;
                    lA2 = __hadd2(lA2, *(__half2*)&pa);
                    lB2 = __hadd2(lB2, *(__half2*)&pb);
                    const int kt = j >> 1, hi = (j & 1) * 2;
                    pf[kt][hi]     = pa;
                    pf[kt][hi + 1] = pb;
                }
            }
            {
                float2 fA = __half22float2(lA2);
                float2 fB = __half22float2(lB2);
                lsumA += fA.x + fA.y;
                lsumB += fB.x + fB.y;
            }

#pragma unroll
            for (int kt = 0; kt < 4; kt++) {
                const int c = kt * 2 + csel;
                uint32_t vh[4][4];
#pragma unroll
                for (int jdp = 0; jdp < 4; jdp++) {
                    const int dim = jdp * 16 + rsel;
                    ldsm4(vh[jdp], vbase + dim * 128 + ((c ^ (dim & 7)) * 16));
                }
#pragma unroll
                for (int jdp = 0; jdp < 4; jdp++) {
                    mma16816(oacc[2 * jdp],     pf[kt], vh[jdp][0], vh[jdp][1]);
                    mma16816(oacc[2 * jdp + 1], pf[kt], vh[jdp][2], vh[jdp][3]);
                }
            }
        }
        __syncthreads();
    }

    lsumA += __shfl_xor_sync(FULL, lsumA, 1);
    lsumA += __shfl_xor_sync(FULL, lsumA, 2);
    lsumB += __shfl_xor_sync(FULL, lsumB, 1);
    lsumB += __shfl_xor_sync(FULL, lsumB, 2);

    const size_t pbase = (((size_t)(b * NQT + qt) * MAXCH + ch) * 128) * HS;
    const int rowA = w * 16 + gid;
#pragma unroll
    for (int jd = 0; jd < 8; jd++) {
        const int col = jd * 8 + tig * 2;
        *(float2*)(&g_part[pbase + (size_t)rowA * HS + col]) =
            make_float2(oacc[jd][0], oacc[jd][1]);
        *(float2*)(&g_part[pbase + (size_t)(rowA + 8) * HS + col]) =
            make_float2(oacc[jd][2], oacc[jd][3]);
    }
    if (tig == 0) {
        const size_t lbase = (((size_t)(b * NQT + qt) * MAXCH + ch) * 128);
        g_l[lbase + rowA] = lsumA;
        g_l[lbase + rowA + 8] = lsumB;
    }
}

// ---------------------------------------------------------------------------
// Kernel 3: merge split-K partials (unchanged)
// ---------------------------------------------------------------------------
__global__ __launch_bounds__(256) void merge_kernel(float* __restrict__ out)
{
    const int bid = blockIdx.x;
    const int rg  = bid & 7;
    const int qt  = (bid >> 3) & 31;
    const int b   = bid >> 8;
    const int nch = qt / 4 + 1;
    const int tid = threadIdx.x;
    const int row = rg * 16 + (tid >> 4);
    const int d0  = (tid & 15) * 4;

    const size_t base = (size_t)(b * NQT + qt) * MAXCH * 128;
    float4 acc = make_float4(0.f, 0.f, 0.f, 0.f);
    float L = 0.f;
#pragma unroll 4
    for (int c = 0; c < nch; c++) {
        L += g_l[base + c * 128 + row];
        const float4 v = *(const float4*)(&g_part[(base + c * 128 + row) * HS + d0]);
        acc.x += v.x; acc.y += v.y; acc.z += v.z; acc.w += v.w;
    }
    const float inv = 1.f / L;
    float* op = out + ((size_t)b * TSEQ + qt * 128 + row) * HS + d0;
    *(float4*)op = make_float4(acc.x * inv, acc.y * inv, acc.z * inv, acc.w * inv);
}

// ---------------------------------------------------------------------------
extern "C" void kernel_launch(void* const* d_in, const int* in_sizes, int n_in,
                              void* d_out, int out_size)
{
    const float* x  = (const float*)d_in[0];
    const float* Wq = (const float*)d_in[1];
    const float* Wk = (const float*)d_in[2];
    const float* Wv = (const float*)d_in[3];
    float* out = (float*)d_out;

    cudaFuncSetAttribute(attn_kernel, cudaFuncAttributeMaxDynamicSharedMemorySize, SMEM_TOTAL);
    cudaFuncSetAttribute(proj_kernel, cudaFuncAttributeMaxDynamicSharedMemorySize, PROJ_SMEM);

    wp_kernel<<<38, 256>>>(Wq, Wk, Wv);
    proj_kernel<<<128, 256, PROJ_SMEM>>>(x);
    attn_kernel<<<BATCH * ITEMS_PER_B, 256, SMEM_TOTAL>>>();
    merge_kernel<<<BATCH * NQT * 8, 256>>>(out);
}